// round 1
// baseline (speedup 1.0000x reference)
#include <cuda_runtime.h>
#include <math.h>

// Problem constants (fixed by the dataset)
#define TOKENS 4096      // B*L
#define SEQ    2048      // L
#define BATCH  2
#define DMODEL 1024
#define NHEAD  16
#define HDIM   64

// Scratch (allocation-free rule: __device__ globals)
__device__ float g_q[TOKENS * DMODEL];
__device__ float g_k[TOKENS * DMODEL];
__device__ float g_v[TOKENS * DMODEL];
__device__ float g_att[TOKENS * DMODEL];

__device__ __forceinline__ float sfn_quant(float x) {
    // q = clip(round(x / 0.5), -8, 8) * 0.5 ; rintf = round-half-even (matches jnp.round)
    float t = rintf(x * 2.0f);
    t = fminf(fmaxf(t, -8.0f), 8.0f);
    return t * 0.5f;
}

// ---------------------------------------------------------------------------
// GEMM-NT: C[m,n] = epilogue( sum_k A[m,k] * W[n,k] + bias[n] )
// A: [M,K] row-major, W: [N,K] row-major. 64x64 block tile, BK=16, 256 thr,
// 4x4 register microtile per thread. Natural smem layout, stride 17 padding.
// ---------------------------------------------------------------------------
template <bool DO_SFN>
__global__ void gemm_nt_kernel(const float* __restrict__ A,
                               const float* __restrict__ W,
                               const float* __restrict__ bias,
                               float* __restrict__ C,
                               int M, int N, int K) {
    __shared__ float As[64 * 17];
    __shared__ float Bs[64 * 17];

    const int tid = threadIdx.x;
    const int tx = tid & 15;       // 0..15 -> 4 output cols each
    const int ty = tid >> 4;       // 0..15 -> 4 output rows each
    const int m0 = blockIdx.y * 64;
    const int n0 = blockIdx.x * 64;

    // loader coords: one float4 per matrix per k-tile
    const int lr  = tid >> 2;            // 0..63 row within tile
    const int lc4 = (tid & 3) << 2;      // 0,4,8,12 col within BK=16

    float acc[4][4];
#pragma unroll
    for (int i = 0; i < 4; ++i)
#pragma unroll
        for (int j = 0; j < 4; ++j) acc[i][j] = 0.0f;

    for (int k0 = 0; k0 < K; k0 += 16) {
        __syncthreads();
        float4 a4 = *(const float4*)(A + (m0 + lr) * K + k0 + lc4);
        float4 b4 = *(const float4*)(W + (n0 + lr) * K + k0 + lc4);
        As[lr * 17 + lc4 + 0] = a4.x;
        As[lr * 17 + lc4 + 1] = a4.y;
        As[lr * 17 + lc4 + 2] = a4.z;
        As[lr * 17 + lc4 + 3] = a4.w;
        Bs[lr * 17 + lc4 + 0] = b4.x;
        Bs[lr * 17 + lc4 + 1] = b4.y;
        Bs[lr * 17 + lc4 + 2] = b4.z;
        Bs[lr * 17 + lc4 + 3] = b4.w;
        __syncthreads();

#pragma unroll
        for (int kk = 0; kk < 16; ++kk) {
            float a[4], b[4];
#pragma unroll
            for (int i = 0; i < 4; ++i) a[i] = As[(ty * 4 + i) * 17 + kk];
#pragma unroll
            for (int j = 0; j < 4; ++j) b[j] = Bs[(tx * 4 + j) * 17 + kk];
#pragma unroll
            for (int i = 0; i < 4; ++i)
#pragma unroll
                for (int j = 0; j < 4; ++j) acc[i][j] = fmaf(a[i], b[j], acc[i][j]);
        }
    }

#pragma unroll
    for (int i = 0; i < 4; ++i) {
        const int m = m0 + ty * 4 + i;
#pragma unroll
        for (int j = 0; j < 4; ++j) {
            const int n = n0 + tx * 4 + j;
            float v = acc[i][j] + bias[n];
            if (DO_SFN) v = sfn_quant(v);
            C[m * N + n] = v;
        }
    }
}

// ---------------------------------------------------------------------------
// QK RMS-norm over head_dim (64), in-place. One warp per (token, head) row.
// ---------------------------------------------------------------------------
__global__ void qknorm_kernel(float* __restrict__ X, const float* __restrict__ g) {
    const int gwarp = (blockIdx.x * blockDim.x + threadIdx.x) >> 5;  // row id
    const int lane = threadIdx.x & 31;
    // rows = TOKENS * NHEAD = 65536
    const int token = gwarp >> 4;
    const int h = gwarp & 15;
    const int base = token * DMODEL + h * HDIM;

    float2 v = *(float2*)(X + base + lane * 2);
    float ss = v.x * v.x + v.y * v.y;
#pragma unroll
    for (int o = 16; o; o >>= 1) ss += __shfl_xor_sync(0xffffffffu, ss, o);
    const float inv = rsqrtf(ss * (1.0f / 64.0f) + 1e-6f);
    const float2 gg = *(const float2*)(g + lane * 2);
    v.x *= inv * gg.x;
    v.y *= inv * gg.y;
    *(float2*)(X + base + lane * 2) = v;
}

// ---------------------------------------------------------------------------
// Flash attention, fp32, non-causal. Per block: one (b, h, 64-row q-tile).
// 64x64 S tile, online softmax, P@V accumulated into 4x4 register tiles.
// Dynamic smem: Qs/Ks/Vs/Ps each [64][65] = 66560 B total.
// ---------------------------------------------------------------------------
__global__ void attn_kernel(const float* __restrict__ Q,
                            const float* __restrict__ K,
                            const float* __restrict__ V,
                            float* __restrict__ O) {
    extern __shared__ float sm[];
    float* Qs = sm;                 // [64][65]
    float* Ks = sm + 64 * 65;       // [64][65]
    float* Vs = sm + 2 * 64 * 65;   // [64][65]
    float* Ps = sm + 3 * 64 * 65;   // [64][65]

    const int tid = threadIdx.x;
    const int tx = tid & 15;
    const int ty = tid >> 4;
    const int qb = blockIdx.x;
    const int h = blockIdx.y;
    const int b = blockIdx.z;

    const int baseQ = (b * SEQ + qb * 64) * DMODEL + h * HDIM;

    // load Q tile (natural layout, stride 65)
#pragma unroll
    for (int it = 0; it < 4; ++it) {
        int lin = tid + it * 256;          // 0..1023 float4 index
        int r = lin >> 4;                  // 0..63
        int c4 = (lin & 15) << 2;          // 0..60
        float4 q4 = *(const float4*)(Q + baseQ + r * DMODEL + c4);
        Qs[r * 65 + c4 + 0] = q4.x;
        Qs[r * 65 + c4 + 1] = q4.y;
        Qs[r * 65 + c4 + 2] = q4.z;
        Qs[r * 65 + c4 + 3] = q4.w;
    }

    float m_i[4], l_i[4], acc[4][4];
#pragma unroll
    for (int i = 0; i < 4; ++i) {
        m_i[i] = -1e30f;
        l_i[i] = 0.0f;
#pragma unroll
        for (int j = 0; j < 4; ++j) acc[i][j] = 0.0f;
    }

    for (int kb = 0; kb < SEQ / 64; ++kb) {
        __syncthreads();   // prev-iteration Ps/Vs/Ks reads complete
        const int baseK = (b * SEQ + kb * 64) * DMODEL + h * HDIM;
#pragma unroll
        for (int it = 0; it < 4; ++it) {
            int lin = tid + it * 256;
            int r = lin >> 4;
            int c4 = (lin & 15) << 2;
            float4 kv = *(const float4*)(K + baseK + r * DMODEL + c4);
            Ks[r * 65 + c4 + 0] = kv.x;
            Ks[r * 65 + c4 + 1] = kv.y;
            Ks[r * 65 + c4 + 2] = kv.z;
            Ks[r * 65 + c4 + 3] = kv.w;
            float4 vv = *(const float4*)(V + baseK + r * DMODEL + c4);
            Vs[r * 65 + c4 + 0] = vv.x;
            Vs[r * 65 + c4 + 1] = vv.y;
            Vs[r * 65 + c4 + 2] = vv.z;
            Vs[r * 65 + c4 + 3] = vv.w;
        }
        __syncthreads();

        // S = Q K^T (4x4 per thread over d=0..63)
        float s[4][4];
#pragma unroll
        for (int i = 0; i < 4; ++i)
#pragma unroll
            for (int j = 0; j < 4; ++j) s[i][j] = 0.0f;

#pragma unroll 8
        for (int d = 0; d < 64; ++d) {
            float a[4], bb[4];
#pragma unroll
            for (int i = 0; i < 4; ++i) a[i] = Qs[(ty * 4 + i) * 65 + d];
#pragma unroll
            for (int j = 0; j < 4; ++j) bb[j] = Ks[(tx * 4 + j) * 65 + d];
#pragma unroll
            for (int i = 0; i < 4; ++i)
#pragma unroll
                for (int j = 0; j < 4; ++j) s[i][j] = fmaf(a[i], bb[j], s[i][j]);
        }

        // online softmax (row reductions across the 16 tx lanes of each half-warp)
#pragma unroll
        for (int i = 0; i < 4; ++i) {
            float rm = -1e30f;
#pragma unroll
            for (int j = 0; j < 4; ++j) {
                s[i][j] *= 0.125f;  // 1/sqrt(64)
                rm = fmaxf(rm, s[i][j]);
            }
#pragma unroll
            for (int o = 8; o; o >>= 1)
                rm = fmaxf(rm, __shfl_xor_sync(0xffffffffu, rm, o));
            const float mn = fmaxf(m_i[i], rm);
            const float alpha = __expf(m_i[i] - mn);
            float rs = 0.0f;
#pragma unroll
            for (int j = 0; j < 4; ++j) {
                s[i][j] = __expf(s[i][j] - mn);  // s now holds P
                rs += s[i][j];
            }
#pragma unroll
            for (int o = 8; o; o >>= 1)
                rs += __shfl_xor_sync(0xffffffffu, rs, o);
            l_i[i] = l_i[i] * alpha + rs;
            m_i[i] = mn;
#pragma unroll
            for (int j = 0; j < 4; ++j) acc[i][j] *= alpha;
        }

        // write P tile (natural layout [qrow][kcol])
#pragma unroll
        for (int i = 0; i < 4; ++i)
#pragma unroll
            for (int j = 0; j < 4; ++j)
                Ps[(ty * 4 + i) * 65 + tx * 4 + j] = s[i][j];
        __syncthreads();

        // O += P @ V
#pragma unroll 8
        for (int k = 0; k < 64; ++k) {
            float p[4], vv[4];
#pragma unroll
            for (int i = 0; i < 4; ++i) p[i] = Ps[(ty * 4 + i) * 65 + k];
#pragma unroll
            for (int j = 0; j < 4; ++j) vv[j] = Vs[k * 65 + tx * 4 + j];
#pragma unroll
            for (int i = 0; i < 4; ++i)
#pragma unroll
                for (int j = 0; j < 4; ++j) acc[i][j] = fmaf(p[i], vv[j], acc[i][j]);
        }
    }

    // epilogue: divide by l, write out (same packed layout as inputs)
#pragma unroll
    for (int i = 0; i < 4; ++i) {
        const float invl = 1.0f / l_i[i];
#pragma unroll
        for (int j = 0; j < 4; ++j)
            O[baseQ + (ty * 4 + i) * DMODEL + tx * 4 + j] = acc[i][j] * invl;
    }
}

// ---------------------------------------------------------------------------

extern "C" void kernel_launch(void* const* d_in, const int* in_sizes, int n_in,
                              void* d_out, int out_size) {
    const float* x  = (const float*)d_in[0];
    const float* Wq = (const float*)d_in[1];
    const float* bq = (const float*)d_in[2];
    const float* Wk = (const float*)d_in[3];
    const float* bk = (const float*)d_in[4];
    const float* Wv = (const float*)d_in[5];
    const float* bv = (const float*)d_in[6];
    const float* Wo = (const float*)d_in[7];
    const float* bo = (const float*)d_in[8];
    const float* gq = (const float*)d_in[9];
    const float* gk = (const float*)d_in[10];
    float* out = (float*)d_out;

    float *qp, *kp, *vp, *ap;
    cudaGetSymbolAddress((void**)&qp, g_q);
    cudaGetSymbolAddress((void**)&kp, g_k);
    cudaGetSymbolAddress((void**)&vp, g_v);
    cudaGetSymbolAddress((void**)&ap, g_att);

    const dim3 gridG(DMODEL / 64, TOKENS / 64);   // (16, 64)
    gemm_nt_kernel<true><<<gridG, 256>>>(x, Wq, bq, qp, TOKENS, DMODEL, DMODEL);
    gemm_nt_kernel<true><<<gridG, 256>>>(x, Wk, bk, kp, TOKENS, DMODEL, DMODEL);
    gemm_nt_kernel<true><<<gridG, 256>>>(x, Wv, bv, vp, TOKENS, DMODEL, DMODEL);

    // 65536 rows, 8 warps per block
    qknorm_kernel<<<(TOKENS * NHEAD) / 8, 256>>>(qp, gq);
    qknorm_kernel<<<(TOKENS * NHEAD) / 8, 256>>>(kp, gk);

    const int smem_bytes = 4 * 64 * 65 * (int)sizeof(float);  // 66560
    cudaFuncSetAttribute(attn_kernel, cudaFuncAttributeMaxDynamicSharedMemorySize,
                         smem_bytes);
    attn_kernel<<<dim3(SEQ / 64, NHEAD, BATCH), 256, smem_bytes>>>(qp, kp, vp, ap);

    gemm_nt_kernel<false><<<gridG, 256>>>(ap, Wo, bo, out, TOKENS, DMODEL, DMODEL);
}

// round 4
// speedup vs baseline: 1.2927x; 1.2927x over previous
#include <cuda_runtime.h>
#include <cuda_bf16.h>
#include <math.h>
#include <stdint.h>

#define TOKENS 4096      // B*L
#define SEQ    2048
#define BATCH  2
#define DMODEL 1024
#define NHEAD  16
#define HDIM   64

#define FIX_CAP (1 << 18)          // fixup list capacity per matrix

// ---------------------------------------------------------------------------
// Scratch (__device__ globals; no allocations allowed)
// ---------------------------------------------------------------------------
__device__ float g_q[TOKENS * DMODEL];
__device__ float g_k[TOKENS * DMODEL];
__device__ float g_v[TOKENS * DMODEL];
__device__ float g_att[TOKENS * DMODEL];

__device__ __nv_bfloat16 g_xhi[TOKENS * DMODEL];
__device__ __nv_bfloat16 g_xlo[TOKENS * DMODEL];
__device__ __nv_bfloat16 g_ahi[TOKENS * DMODEL];
__device__ __nv_bfloat16 g_alo[TOKENS * DMODEL];
__device__ __nv_bfloat16 g_wqhi[DMODEL * DMODEL];
__device__ __nv_bfloat16 g_wqlo[DMODEL * DMODEL];
__device__ __nv_bfloat16 g_wkhi[DMODEL * DMODEL];
__device__ __nv_bfloat16 g_wklo[DMODEL * DMODEL];
__device__ __nv_bfloat16 g_wvhi[DMODEL * DMODEL];
__device__ __nv_bfloat16 g_wvlo[DMODEL * DMODEL];
__device__ __nv_bfloat16 g_wohi[DMODEL * DMODEL];
__device__ __nv_bfloat16 g_wolo[DMODEL * DMODEL];

__device__ int g_fixcnt[4];
__device__ uint32_t g_fixlist[3 * FIX_CAP];

// ---------------------------------------------------------------------------
// helpers
// ---------------------------------------------------------------------------
__device__ __forceinline__ uint32_t smem_u32(const void* p) {
    uint32_t a;
    asm("{ .reg .u64 t; cvta.to.shared.u64 t, %1; cvt.u32.u64 %0, t; }" : "=r"(a) : "l"(p));
    return a;
}

#define CP16(s, g)  asm volatile("cp.async.cg.shared.global [%0], [%1], 16;" :: "r"(s), "l"(g) : "memory")
#define CP_COMMIT() asm volatile("cp.async.commit_group;" ::: "memory")
#define CP_WAIT(n)  asm volatile("cp.async.wait_group %0;" :: "n"(n) : "memory")

#define LDSM4(r0, r1, r2, r3, a) \
    asm volatile("ldmatrix.sync.aligned.m8n8.x4.shared.b16 {%0,%1,%2,%3}, [%4];" \
        : "=r"(r0), "=r"(r1), "=r"(r2), "=r"(r3) : "r"(a))
#define LDSM2(r0, r1, a) \
    asm volatile("ldmatrix.sync.aligned.m8n8.x2.shared.b16 {%0,%1}, [%2];" \
        : "=r"(r0), "=r"(r1) : "r"(a))

#define MMA_BF16(d, a, b) \
    asm volatile("mma.sync.aligned.m16n8k16.row.col.f32.bf16.bf16.f32 " \
        "{%0,%1,%2,%3}, {%4,%5,%6,%7}, {%8,%9}, {%0,%1,%2,%3};" \
        : "+f"((d)[0]), "+f"((d)[1]), "+f"((d)[2]), "+f"((d)[3]) \
        : "r"((a)[0]), "r"((a)[1]), "r"((a)[2]), "r"((a)[3]), "r"((b)[0]), "r"((b)[1]))

__device__ __forceinline__ float sfn_quant(float x) {
    float t = rintf(x * 2.0f);
    t = fminf(fmaxf(t, -8.0f), 8.0f);
    return t * 0.5f;
}

// boundary risk check in t = 2*v units (boundaries at half-integers, spacing 1)
__device__ __forceinline__ bool sfn_risky(float v) {
    float t = v * 2.0f;
    float d = 0.5f - fabsf(t - rintf(t));
    return (d < 1e-3f) && (fabsf(t) < 8.6f);
}

// ---------------------------------------------------------------------------
// fp32 -> (bf16 hi, bf16 lo) split
// ---------------------------------------------------------------------------
__global__ void split_kernel(const float* __restrict__ X,
                             __nv_bfloat16* __restrict__ hi,
                             __nv_bfloat16* __restrict__ lo, int n4) {
    int i = blockIdx.x * blockDim.x + threadIdx.x;
    if (i >= n4) return;
    float4 v = ((const float4*)X)[i];
    __nv_bfloat16 h0 = __float2bfloat16(v.x);
    __nv_bfloat16 h1 = __float2bfloat16(v.y);
    __nv_bfloat16 h2 = __float2bfloat16(v.z);
    __nv_bfloat16 h3 = __float2bfloat16(v.w);
    __nv_bfloat16 l0 = __float2bfloat16(v.x - __bfloat162float(h0));
    __nv_bfloat16 l1 = __float2bfloat16(v.y - __bfloat162float(h1));
    __nv_bfloat16 l2 = __float2bfloat16(v.z - __bfloat162float(h2));
    __nv_bfloat16 l3 = __float2bfloat16(v.w - __bfloat162float(h3));
    ((__nv_bfloat162*)hi)[2 * i + 0] = __halves2bfloat162(h0, h1);
    ((__nv_bfloat162*)hi)[2 * i + 1] = __halves2bfloat162(h2, h3);
    ((__nv_bfloat162*)lo)[2 * i + 0] = __halves2bfloat162(l0, l1);
    ((__nv_bfloat162*)lo)[2 * i + 1] = __halves2bfloat162(l2, l3);
}

// ---------------------------------------------------------------------------
// mma.sync bf16x3 GEMM-NT: C[m,n] = epi( sum_k A[m,k] W[n,k] + bias[n] )
// BM=128, BN=128, BK=32, 256 threads (8 warps as 4m x 2n), warp tile 32x64.
// blockIdx.z selects among up to 3 (W, bias, C) sets sharing the same A.
// When DO_SFN: flags near-boundary outputs into the fixup list.
// ---------------------------------------------------------------------------
#define BM 128
#define BN 128
#define BK 32
#define NCHUNK (DMODEL / BK)          // 32
#define ROWB 80
#define MAT_BYTES (128 * ROWB)
#define OFF_AHI 0
#define OFF_ALO (1 * MAT_BYTES)
#define OFF_WHI (2 * MAT_BYTES)
#define OFF_WLO (3 * MAT_BYTES)
#define STAGE_BYTES (4 * MAT_BYTES)
#define GEMM_SMEM (2 * STAGE_BYTES)   // 81920

__device__ __forceinline__ void gemm_issue_loads(
    uint32_t sb, int buf, int chunk,
    const __nv_bfloat16* __restrict__ Ahi, const __nv_bfloat16* __restrict__ Alo,
    const __nv_bfloat16* __restrict__ Whi, const __nv_bfloat16* __restrict__ Wlo,
    int m0, int n0, int tid) {
    const uint32_t b = sb + buf * STAGE_BYTES;
    const int k0 = chunk * BK;
#pragma unroll
    for (int j = 0; j < 2; ++j) {
        int slot = tid + j * 256;
        int r = slot >> 2;
        int c = slot & 3;
        uint32_t so = (uint32_t)(r * ROWB + c * 16);
        size_t ga = (size_t)(m0 + r) * DMODEL + k0 + c * 8;
        size_t gw = (size_t)(n0 + r) * DMODEL + k0 + c * 8;
        CP16(b + OFF_AHI + so, Ahi + ga);
        CP16(b + OFF_ALO + so, Alo + ga);
        CP16(b + OFF_WHI + so, Whi + gw);
        CP16(b + OFF_WLO + so, Wlo + gw);
    }
}

template <bool DO_SFN>
__global__ void __launch_bounds__(256, 1)
gemm_mma_kernel(const __nv_bfloat16* __restrict__ Ahi, const __nv_bfloat16* __restrict__ Alo,
                const __nv_bfloat16* __restrict__ W0h, const __nv_bfloat16* __restrict__ W0l,
                const float* __restrict__ b0, float* __restrict__ C0,
                const __nv_bfloat16* __restrict__ W1h, const __nv_bfloat16* __restrict__ W1l,
                const float* __restrict__ b1, float* __restrict__ C1,
                const __nv_bfloat16* __restrict__ W2h, const __nv_bfloat16* __restrict__ W2l,
                const float* __restrict__ b2, float* __restrict__ C2,
                int* __restrict__ fixcnt, uint32_t* __restrict__ fixlist) {
    const __nv_bfloat16 *Whi, *Wlo;
    const float* bias;
    float* C;
    const int z = blockIdx.z;
    if (z == 0)      { Whi = W0h; Wlo = W0l; bias = b0; C = C0; }
    else if (z == 1) { Whi = W1h; Wlo = W1l; bias = b1; C = C1; }
    else             { Whi = W2h; Wlo = W2l; bias = b2; C = C2; }

    extern __shared__ char smem[];
    const uint32_t sb = smem_u32(smem);
    const int tid = threadIdx.x;
    const int wid = tid >> 5;
    const int lane = tid & 31;
    const int warp_m = wid & 3;
    const int warp_n = wid >> 2;
    const int m0 = blockIdx.y * BM;
    const int n0 = blockIdx.x * BN;

    float acc[2][8][4];
#pragma unroll
    for (int mt = 0; mt < 2; ++mt)
#pragma unroll
        for (int nt = 0; nt < 8; ++nt)
#pragma unroll
            for (int e = 0; e < 4; ++e) acc[mt][nt][e] = 0.0f;

    const uint32_t a_row = (uint32_t)(warp_m * 32 + (lane & 15));
    const uint32_t a_kb = (uint32_t)(((lane >> 4) & 1) * 16);
    const uint32_t b_row = (uint32_t)(warp_n * 64 + (lane & 7));
    const uint32_t b_kb = (uint32_t)(((lane >> 3) & 1) * 16);

    gemm_issue_loads(sb, 0, 0, Ahi, Alo, Whi, Wlo, m0, n0, tid);
    CP_COMMIT();
    gemm_issue_loads(sb, 1, 1, Ahi, Alo, Whi, Wlo, m0, n0, tid);
    CP_COMMIT();

    for (int i = 0; i < NCHUNK; ++i) {
        if (i + 1 < NCHUNK) { CP_WAIT(1); } else { CP_WAIT(0); }
        __syncthreads();

        const uint32_t st = sb + (i & 1) * STAGE_BYTES;
        const uint32_t baseAhi = st + OFF_AHI + a_row * ROWB + a_kb;
        const uint32_t baseAlo = st + OFF_ALO + a_row * ROWB + a_kb;
        const uint32_t baseWhi = st + OFF_WHI + b_row * ROWB + b_kb;
        const uint32_t baseWlo = st + OFF_WLO + b_row * ROWB + b_kb;

#pragma unroll
        for (int ks = 0; ks < 2; ++ks) {
            uint32_t ahi[2][4], alo[2][4];
#pragma unroll
            for (int mt = 0; mt < 2; ++mt) {
                uint32_t ao = (uint32_t)(mt * 16 * ROWB + ks * 32);
                LDSM4(ahi[mt][0], ahi[mt][1], ahi[mt][2], ahi[mt][3], baseAhi + ao);
                LDSM4(alo[mt][0], alo[mt][1], alo[mt][2], alo[mt][3], baseAlo + ao);
            }
#pragma unroll
            for (int nt = 0; nt < 8; ++nt) {
                uint32_t bo = (uint32_t)(nt * 8 * ROWB + ks * 32);
                uint32_t whi[2], wlo[2];
                LDSM2(whi[0], whi[1], baseWhi + bo);
                LDSM2(wlo[0], wlo[1], baseWlo + bo);
                MMA_BF16(acc[0][nt], ahi[0], whi);
                MMA_BF16(acc[1][nt], ahi[1], whi);
                MMA_BF16(acc[0][nt], ahi[0], wlo);
                MMA_BF16(acc[1][nt], ahi[1], wlo);
                MMA_BF16(acc[0][nt], alo[0], whi);
                MMA_BF16(acc[1][nt], alo[1], whi);
            }
        }
        __syncthreads();

        if (i + 2 < NCHUNK) {
            gemm_issue_loads(sb, i & 1, i + 2, Ahi, Alo, Whi, Wlo, m0, n0, tid);
            CP_COMMIT();
        }
    }

    // Epilogue: fused bias (+sfn with boundary flagging), float2 stores.
    const int row_base = m0 + warp_m * 32 + (lane >> 2);
    const int col_base = n0 + warp_n * 64 + (lane & 3) * 2;
    int* cnt = fixcnt + z;
    uint32_t* list = fixlist + (size_t)z * FIX_CAP;
#pragma unroll
    for (int mt = 0; mt < 2; ++mt) {
#pragma unroll
        for (int nt = 0; nt < 8; ++nt) {
            const int col = col_base + nt * 8;
            const float bb0 = __ldg(bias + col);
            const float bb1 = __ldg(bias + col + 1);
            const int r0 = row_base + mt * 16;
            float v0 = acc[mt][nt][0] + bb0;
            float v1 = acc[mt][nt][1] + bb1;
            float v2 = acc[mt][nt][2] + bb0;
            float v3 = acc[mt][nt][3] + bb1;
            if (DO_SFN) {
                if (sfn_risky(v0)) { int ix = atomicAdd(cnt, 1); if (ix < FIX_CAP) list[ix] = ((uint32_t)r0 << 10) | col; }
                if (sfn_risky(v1)) { int ix = atomicAdd(cnt, 1); if (ix < FIX_CAP) list[ix] = ((uint32_t)r0 << 10) | (col + 1); }
                if (sfn_risky(v2)) { int ix = atomicAdd(cnt, 1); if (ix < FIX_CAP) list[ix] = ((uint32_t)(r0 + 8) << 10) | col; }
                if (sfn_risky(v3)) { int ix = atomicAdd(cnt, 1); if (ix < FIX_CAP) list[ix] = ((uint32_t)(r0 + 8) << 10) | (col + 1); }
                v0 = sfn_quant(v0); v1 = sfn_quant(v1);
                v2 = sfn_quant(v2); v3 = sfn_quant(v3);
            }
            *(float2*)(C + (size_t)r0 * DMODEL + col) = make_float2(v0, v1);
            *(float2*)(C + (size_t)(r0 + 8) * DMODEL + col) = make_float2(v2, v3);
        }
    }
}

// ---------------------------------------------------------------------------
// Fixup: recompute flagged elements exactly in fp32 (one warp per element).
// blockIdx.y picks the matrix (q/k/v).
// ---------------------------------------------------------------------------
__global__ void fixup_kernel(const float* __restrict__ X,
                             const float* __restrict__ W0, const float* __restrict__ bia0, float* __restrict__ C0,
                             const float* __restrict__ W1, const float* __restrict__ bia1, float* __restrict__ C1,
                             const float* __restrict__ W2, const float* __restrict__ bia2, float* __restrict__ C2,
                             const int* __restrict__ fixcnt, const uint32_t* __restrict__ fixlist) {
    const int z = blockIdx.y;
    const float* W;
    const float* bias;
    float* C;
    if (z == 0)      { W = W0; bias = bia0; C = C0; }
    else if (z == 1) { W = W1; bias = bia1; C = C1; }
    else             { W = W2; bias = bia2; C = C2; }

    int n = fixcnt[z];
    if (n > FIX_CAP) n = FIX_CAP;
    const uint32_t* list = fixlist + (size_t)z * FIX_CAP;

    const int lane = threadIdx.x & 31;
    const int warp = (blockIdx.x * blockDim.x + threadIdx.x) >> 5;
    const int nwarps = (gridDim.x * blockDim.x) >> 5;

    for (int e = warp; e < n; e += nwarps) {
        uint32_t u = list[e];
        int row = u >> 10;
        int col = u & 1023;
        const float* xr = X + (size_t)row * DMODEL;
        const float* wr = W + (size_t)col * DMODEL;
        float s = 0.0f;
#pragma unroll
        for (int j = 0; j < DMODEL / 32; ++j)
            s = fmaf(xr[lane + j * 32], wr[lane + j * 32], s);
#pragma unroll
        for (int o = 16; o; o >>= 1) s += __shfl_xor_sync(0xffffffffu, s, o);
        if (lane == 0)
            C[(size_t)row * DMODEL + col] = sfn_quant(s + bias[col]);
    }
}

// ---------------------------------------------------------------------------
// QK RMS-norm
// ---------------------------------------------------------------------------
__global__ void qknorm_kernel(float* __restrict__ X, const float* __restrict__ g) {
    const int gwarp = (blockIdx.x * blockDim.x + threadIdx.x) >> 5;
    const int lane = threadIdx.x & 31;
    const int token = gwarp >> 4;
    const int h = gwarp & 15;
    const int base = token * DMODEL + h * HDIM;

    float2 v = *(float2*)(X + base + lane * 2);
    float ss = v.x * v.x + v.y * v.y;
#pragma unroll
    for (int o = 16; o; o >>= 1) ss += __shfl_xor_sync(0xffffffffu, ss, o);
    const float inv = rsqrtf(ss * (1.0f / 64.0f) + 1e-6f);
    const float2 gg = *(const float2*)(g + lane * 2);
    v.x *= inv * gg.x;
    v.y *= inv * gg.y;
    *(float2*)(X + base + lane * 2) = v;
}

// ---------------------------------------------------------------------------
// Flash attention fp32 (unchanged; known-good)
// ---------------------------------------------------------------------------
__global__ void attn_kernel(const float* __restrict__ Q,
                            const float* __restrict__ K,
                            const float* __restrict__ V,
                            float* __restrict__ O) {
    extern __shared__ float sm[];
    float* Qs = sm;
    float* Ks = sm + 64 * 65;
    float* Vs = sm + 2 * 64 * 65;
    float* Ps = sm + 3 * 64 * 65;

    const int tid = threadIdx.x;
    const int tx = tid & 15;
    const int ty = tid >> 4;
    const int qb = blockIdx.x;
    const int h = blockIdx.y;
    const int b = blockIdx.z;

    const int baseQ = (b * SEQ + qb * 64) * DMODEL + h * HDIM;

#pragma unroll
    for (int it = 0; it < 4; ++it) {
        int lin = tid + it * 256;
        int r = lin >> 4;
        int c4 = (lin & 15) << 2;
        float4 q4 = *(const float4*)(Q + baseQ + r * DMODEL + c4);
        Qs[r * 65 + c4 + 0] = q4.x;
        Qs[r * 65 + c4 + 1] = q4.y;
        Qs[r * 65 + c4 + 2] = q4.z;
        Qs[r * 65 + c4 + 3] = q4.w;
    }

    float m_i[4], l_i[4], acc[4][4];
#pragma unroll
    for (int i = 0; i < 4; ++i) {
        m_i[i] = -1e30f;
        l_i[i] = 0.0f;
#pragma unroll
        for (int j = 0; j < 4; ++j) acc[i][j] = 0.0f;
    }

    for (int kb = 0; kb < SEQ / 64; ++kb) {
        __syncthreads();
        const int baseK = (b * SEQ + kb * 64) * DMODEL + h * HDIM;
#pragma unroll
        for (int it = 0; it < 4; ++it) {
            int lin = tid + it * 256;
            int r = lin >> 4;
            int c4 = (lin & 15) << 2;
            float4 kv = *(const float4*)(K + baseK + r * DMODEL + c4);
            Ks[r * 65 + c4 + 0] = kv.x;
            Ks[r * 65 + c4 + 1] = kv.y;
            Ks[r * 65 + c4 + 2] = kv.z;
            Ks[r * 65 + c4 + 3] = kv.w;
            float4 vv = *(const float4*)(V + baseK + r * DMODEL + c4);
            Vs[r * 65 + c4 + 0] = vv.x;
            Vs[r * 65 + c4 + 1] = vv.y;
            Vs[r * 65 + c4 + 2] = vv.z;
            Vs[r * 65 + c4 + 3] = vv.w;
        }
        __syncthreads();

        float s[4][4];
#pragma unroll
        for (int i = 0; i < 4; ++i)
#pragma unroll
            for (int j = 0; j < 4; ++j) s[i][j] = 0.0f;

#pragma unroll 8
        for (int d = 0; d < 64; ++d) {
            float a[4], bb[4];
#pragma unroll
            for (int i = 0; i < 4; ++i) a[i] = Qs[(ty * 4 + i) * 65 + d];
#pragma unroll
            for (int j = 0; j < 4; ++j) bb[j] = Ks[(tx * 4 + j) * 65 + d];
#pragma unroll
            for (int i = 0; i < 4; ++i)
#pragma unroll
                for (int j = 0; j < 4; ++j) s[i][j] = fmaf(a[i], bb[j], s[i][j]);
        }

#pragma unroll
        for (int i = 0; i < 4; ++i) {
            float rm = -1e30f;
#pragma unroll
            for (int j = 0; j < 4; ++j) {
                s[i][j] *= 0.125f;
                rm = fmaxf(rm, s[i][j]);
            }
#pragma unroll
            for (int o = 8; o; o >>= 1)
                rm = fmaxf(rm, __shfl_xor_sync(0xffffffffu, rm, o));
            const float mn = fmaxf(m_i[i], rm);
            const float alpha = __expf(m_i[i] - mn);
            float rs = 0.0f;
#pragma unroll
            for (int j = 0; j < 4; ++j) {
                s[i][j] = __expf(s[i][j] - mn);
                rs += s[i][j];
            }
#pragma unroll
            for (int o = 8; o; o >>= 1)
                rs += __shfl_xor_sync(0xffffffffu, rs, o);
            l_i[i] = l_i[i] * alpha + rs;
            m_i[i] = mn;
#pragma unroll
            for (int j = 0; j < 4; ++j) acc[i][j] *= alpha;
        }

#pragma unroll
        for (int i = 0; i < 4; ++i)
#pragma unroll
            for (int j = 0; j < 4; ++j)
                Ps[(ty * 4 + i) * 65 + tx * 4 + j] = s[i][j];
        __syncthreads();

#pragma unroll 8
        for (int k = 0; k < 64; ++k) {
            float p[4], vv[4];
#pragma unroll
            for (int i = 0; i < 4; ++i) p[i] = Ps[(ty * 4 + i) * 65 + k];
#pragma unroll
            for (int j = 0; j < 4; ++j) vv[j] = Vs[k * 65 + tx * 4 + j];
#pragma unroll
            for (int i = 0; i < 4; ++i)
#pragma unroll
                for (int j = 0; j < 4; ++j) acc[i][j] = fmaf(p[i], vv[j], acc[i][j]);
        }
    }

#pragma unroll
    for (int i = 0; i < 4; ++i) {
        const float invl = 1.0f / l_i[i];
#pragma unroll
        for (int j = 0; j < 4; ++j)
            O[baseQ + (ty * 4 + i) * DMODEL + tx * 4 + j] = acc[i][j] * invl;
    }
}

// ---------------------------------------------------------------------------

extern "C" void kernel_launch(void* const* d_in, const int* in_sizes, int n_in,
                              void* d_out, int out_size) {
    const float* x  = (const float*)d_in[0];
    const float* Wq = (const float*)d_in[1];
    const float* bq = (const float*)d_in[2];
    const float* Wk = (const float*)d_in[3];
    const float* bk = (const float*)d_in[4];
    const float* Wv = (const float*)d_in[5];
    const float* bv = (const float*)d_in[6];
    const float* Wo = (const float*)d_in[7];
    const float* bo = (const float*)d_in[8];
    const float* gq = (const float*)d_in[9];
    const float* gk = (const float*)d_in[10];
    float* out = (float*)d_out;

    float *qp, *kp, *vp, *ap;
    cudaGetSymbolAddress((void**)&qp, g_q);
    cudaGetSymbolAddress((void**)&kp, g_k);
    cudaGetSymbolAddress((void**)&vp, g_v);
    cudaGetSymbolAddress((void**)&ap, g_att);
    __nv_bfloat16 *xhi, *xlo, *ahi, *alo;
    __nv_bfloat16 *wqh, *wql, *wkh, *wkl, *wvh, *wvl, *woh, *wol;
    cudaGetSymbolAddress((void**)&xhi, g_xhi);
    cudaGetSymbolAddress((void**)&xlo, g_xlo);
    cudaGetSymbolAddress((void**)&ahi, g_ahi);
    cudaGetSymbolAddress((void**)&alo, g_alo);
    cudaGetSymbolAddress((void**)&wqh, g_wqhi);
    cudaGetSymbolAddress((void**)&wql, g_wqlo);
    cudaGetSymbolAddress((void**)&wkh, g_wkhi);
    cudaGetSymbolAddress((void**)&wkl, g_wklo);
    cudaGetSymbolAddress((void**)&wvh, g_wvhi);
    cudaGetSymbolAddress((void**)&wvl, g_wvlo);
    cudaGetSymbolAddress((void**)&woh, g_wohi);
    cudaGetSymbolAddress((void**)&wol, g_wolo);
    int* fixcnt;
    uint32_t* fixlist;
    cudaGetSymbolAddress((void**)&fixcnt, g_fixcnt);
    cudaGetSymbolAddress((void**)&fixlist, g_fixlist);

    cudaFuncSetAttribute(gemm_mma_kernel<true>,
                         cudaFuncAttributeMaxDynamicSharedMemorySize, GEMM_SMEM);
    cudaFuncSetAttribute(gemm_mma_kernel<false>,
                         cudaFuncAttributeMaxDynamicSharedMemorySize, GEMM_SMEM);

    cudaMemsetAsync(fixcnt, 0, 4 * sizeof(int));

    const int NX4 = TOKENS * DMODEL / 4;
    const int NW4 = DMODEL * DMODEL / 4;
    split_kernel<<<NX4 / 256, 256>>>(x, xhi, xlo, NX4);
    split_kernel<<<NW4 / 256, 256>>>(Wq, wqh, wql, NW4);
    split_kernel<<<NW4 / 256, 256>>>(Wk, wkh, wkl, NW4);
    split_kernel<<<NW4 / 256, 256>>>(Wv, wvh, wvl, NW4);
    split_kernel<<<NW4 / 256, 256>>>(Wo, woh, wol, NW4);

    // Fused QKV projections (grid.z = 3) + boundary flagging
    gemm_mma_kernel<true><<<dim3(DMODEL / BN, TOKENS / BM, 3), 256, GEMM_SMEM>>>(
        xhi, xlo,
        wqh, wql, bq, qp,
        wkh, wkl, bk, kp,
        wvh, wvl, bv, vp,
        fixcnt, fixlist);

    // Exact fp32 fixup of near-boundary elements
    fixup_kernel<<<dim3(32, 3), 256>>>(x, Wq, bq, qp, Wk, bk, kp, Wv, bv, vp,
                                       fixcnt, fixlist);

    qknorm_kernel<<<(TOKENS * NHEAD) / 8, 256>>>(qp, gq);
    qknorm_kernel<<<(TOKENS * NHEAD) / 8, 256>>>(kp, gk);

    const int attn_smem = 4 * 64 * 65 * (int)sizeof(float);
    cudaFuncSetAttribute(attn_kernel, cudaFuncAttributeMaxDynamicSharedMemorySize,
                         attn_smem);
    attn_kernel<<<dim3(SEQ / 64, NHEAD, BATCH), 256, attn_smem>>>(qp, kp, vp, ap);

    split_kernel<<<NX4 / 256, 256>>>(ap, ahi, alo, NX4);
    // O-projection: smooth (no quantizer) -> bf16x3, no fixup
    gemm_mma_kernel<false><<<dim3(DMODEL / BN, TOKENS / BM, 1), 256, GEMM_SMEM>>>(
        ahi, alo,
        woh, wol, bo, out,
        woh, wol, bo, out,
        woh, wol, bo, out,
        fixcnt + 3, fixlist);
}

// round 5
// speedup vs baseline: 2.7583x; 2.1338x over previous
#include <cuda_runtime.h>
#include <cuda_bf16.h>
#include <math.h>
#include <stdint.h>

#define TOKENS 4096      // B*L
#define SEQ    2048
#define BATCH  2
#define DMODEL 1024
#define NHEAD  16
#define HDIM   64

#define FIX_CAP (1 << 18)

// ---------------------------------------------------------------------------
// Scratch (__device__ globals)
// ---------------------------------------------------------------------------
__device__ __nv_bfloat16 g_qb[TOKENS * DMODEL];    // raw q (sfn, exact bf16)
__device__ __nv_bfloat16 g_kb[TOKENS * DMODEL];    // raw k (exact)
__device__ __nv_bfloat16 g_vb[TOKENS * DMODEL];    // raw v (exact)
__device__ __nv_bfloat16 g_qthi[TOKENS * DMODEL];  // q*(gq*gk) hi
__device__ __nv_bfloat16 g_qtlo[TOKENS * DMODEL];  // q*(gq*gk) lo
__device__ float g_irq[NHEAD * TOKENS];            // [h][token] 1/rms(q)
__device__ float g_irk[NHEAD * TOKENS];            // [h][token] 1/rms(k)

__device__ __nv_bfloat16 g_xhi[TOKENS * DMODEL];
__device__ __nv_bfloat16 g_xlo[TOKENS * DMODEL];
__device__ __nv_bfloat16 g_ahi[TOKENS * DMODEL];   // attn out hi
__device__ __nv_bfloat16 g_alo[TOKENS * DMODEL];   // attn out lo
__device__ __nv_bfloat16 g_wqhi[DMODEL * DMODEL];
__device__ __nv_bfloat16 g_wqlo[DMODEL * DMODEL];
__device__ __nv_bfloat16 g_wkhi[DMODEL * DMODEL];
__device__ __nv_bfloat16 g_wklo[DMODEL * DMODEL];
__device__ __nv_bfloat16 g_wvhi[DMODEL * DMODEL];
__device__ __nv_bfloat16 g_wvlo[DMODEL * DMODEL];
__device__ __nv_bfloat16 g_wohi[DMODEL * DMODEL];
__device__ __nv_bfloat16 g_wolo[DMODEL * DMODEL];

__device__ int g_fixcnt[4];
__device__ uint32_t g_fixlist[3 * FIX_CAP];

// ---------------------------------------------------------------------------
// helpers
// ---------------------------------------------------------------------------
__device__ __forceinline__ uint32_t smem_u32(const void* p) {
    uint32_t a;
    asm("{ .reg .u64 t; cvta.to.shared.u64 t, %1; cvt.u32.u64 %0, t; }" : "=r"(a) : "l"(p));
    return a;
}

#define CP16(s, g)  asm volatile("cp.async.cg.shared.global [%0], [%1], 16;" :: "r"(s), "l"(g) : "memory")
#define CP_COMMIT() asm volatile("cp.async.commit_group;" ::: "memory")
#define CP_WAIT(n)  asm volatile("cp.async.wait_group %0;" :: "n"(n) : "memory")

#define LDSM4(r0, r1, r2, r3, a) \
    asm volatile("ldmatrix.sync.aligned.m8n8.x4.shared.b16 {%0,%1,%2,%3}, [%4];" \
        : "=r"(r0), "=r"(r1), "=r"(r2), "=r"(r3) : "r"(a))
#define LDSM4T(r0, r1, r2, r3, a) \
    asm volatile("ldmatrix.sync.aligned.m8n8.x4.trans.shared.b16 {%0,%1,%2,%3}, [%4];" \
        : "=r"(r0), "=r"(r1), "=r"(r2), "=r"(r3) : "r"(a))
#define LDSM2(r0, r1, a) \
    asm volatile("ldmatrix.sync.aligned.m8n8.x2.shared.b16 {%0,%1}, [%2];" \
        : "=r"(r0), "=r"(r1) : "r"(a))

#define MMA_BF16(d, a, b) \
    asm volatile("mma.sync.aligned.m16n8k16.row.col.f32.bf16.bf16.f32 " \
        "{%0,%1,%2,%3}, {%4,%5,%6,%7}, {%8,%9}, {%0,%1,%2,%3};" \
        : "+f"((d)[0]), "+f"((d)[1]), "+f"((d)[2]), "+f"((d)[3]) \
        : "r"((a)[0]), "r"((a)[1]), "r"((a)[2]), "r"((a)[3]), "r"((b)[0]), "r"((b)[1]))

__device__ __forceinline__ float sfn_quant(float x) {
    float t = rintf(x * 2.0f);
    t = fminf(fmaxf(t, -8.0f), 8.0f);
    return t * 0.5f;
}
__device__ __forceinline__ bool sfn_risky(float v) {
    float t = v * 2.0f;
    float d = 0.5f - fabsf(t - rintf(t));
    return (d < 1e-3f) && (fabsf(t) < 8.6f);
}
__device__ __forceinline__ uint32_t packbf(float lo, float hi) {
    __nv_bfloat162 t = __floats2bfloat162_rn(lo, hi);
    return *reinterpret_cast<uint32_t*>(&t);
}

// ---------------------------------------------------------------------------
// fp32 -> (bf16 hi, bf16 lo) split
// ---------------------------------------------------------------------------
__global__ void split_kernel(const float* __restrict__ X,
                             __nv_bfloat16* __restrict__ hi,
                             __nv_bfloat16* __restrict__ lo, int n4) {
    int i = blockIdx.x * blockDim.x + threadIdx.x;
    if (i >= n4) return;
    float4 v = ((const float4*)X)[i];
    __nv_bfloat16 h0 = __float2bfloat16(v.x);
    __nv_bfloat16 h1 = __float2bfloat16(v.y);
    __nv_bfloat16 h2 = __float2bfloat16(v.z);
    __nv_bfloat16 h3 = __float2bfloat16(v.w);
    __nv_bfloat16 l0 = __float2bfloat16(v.x - __bfloat162float(h0));
    __nv_bfloat16 l1 = __float2bfloat16(v.y - __bfloat162float(h1));
    __nv_bfloat16 l2 = __float2bfloat16(v.z - __bfloat162float(h2));
    __nv_bfloat16 l3 = __float2bfloat16(v.w - __bfloat162float(h3));
    ((__nv_bfloat162*)hi)[2 * i + 0] = __halves2bfloat162(h0, h1);
    ((__nv_bfloat162*)hi)[2 * i + 1] = __halves2bfloat162(h2, h3);
    ((__nv_bfloat162*)lo)[2 * i + 0] = __halves2bfloat162(l0, l1);
    ((__nv_bfloat162*)lo)[2 * i + 1] = __halves2bfloat162(l2, l3);
}

// ---------------------------------------------------------------------------
// mma.sync bf16x3 GEMM-NT (as round 4). DO_SFN -> bf16 output + flags;
// else fp32 output.
// ---------------------------------------------------------------------------
#define BM 128
#define BN 128
#define BK 32
#define NCHUNK (DMODEL / BK)
#define ROWB 80
#define MAT_BYTES (128 * ROWB)
#define OFF_AHI 0
#define OFF_ALO (1 * MAT_BYTES)
#define OFF_WHI (2 * MAT_BYTES)
#define OFF_WLO (3 * MAT_BYTES)
#define STAGE_BYTES (4 * MAT_BYTES)
#define GEMM_SMEM (2 * STAGE_BYTES)

__device__ __forceinline__ void gemm_issue_loads(
    uint32_t sb, int buf, int chunk,
    const __nv_bfloat16* __restrict__ Ahi, const __nv_bfloat16* __restrict__ Alo,
    const __nv_bfloat16* __restrict__ Whi, const __nv_bfloat16* __restrict__ Wlo,
    int m0, int n0, int tid) {
    const uint32_t b = sb + buf * STAGE_BYTES;
    const int k0 = chunk * BK;
#pragma unroll
    for (int j = 0; j < 2; ++j) {
        int slot = tid + j * 256;
        int r = slot >> 2;
        int c = slot & 3;
        uint32_t so = (uint32_t)(r * ROWB + c * 16);
        size_t ga = (size_t)(m0 + r) * DMODEL + k0 + c * 8;
        size_t gw = (size_t)(n0 + r) * DMODEL + k0 + c * 8;
        CP16(b + OFF_AHI + so, Ahi + ga);
        CP16(b + OFF_ALO + so, Alo + ga);
        CP16(b + OFF_WHI + so, Whi + gw);
        CP16(b + OFF_WLO + so, Wlo + gw);
    }
}

template <bool DO_SFN>
__global__ void __launch_bounds__(256, 1)
gemm_mma_kernel(const __nv_bfloat16* __restrict__ Ahi, const __nv_bfloat16* __restrict__ Alo,
                const __nv_bfloat16* __restrict__ W0h, const __nv_bfloat16* __restrict__ W0l,
                const float* __restrict__ b0, void* __restrict__ C0v,
                const __nv_bfloat16* __restrict__ W1h, const __nv_bfloat16* __restrict__ W1l,
                const float* __restrict__ b1, void* __restrict__ C1v,
                const __nv_bfloat16* __restrict__ W2h, const __nv_bfloat16* __restrict__ W2l,
                const float* __restrict__ b2, void* __restrict__ C2v,
                int* __restrict__ fixcnt, uint32_t* __restrict__ fixlist) {
    const __nv_bfloat16 *Whi, *Wlo;
    const float* bias;
    void* Cv;
    const int z = blockIdx.z;
    if (z == 0)      { Whi = W0h; Wlo = W0l; bias = b0; Cv = C0v; }
    else if (z == 1) { Whi = W1h; Wlo = W1l; bias = b1; Cv = C1v; }
    else             { Whi = W2h; Wlo = W2l; bias = b2; Cv = C2v; }

    extern __shared__ char smem[];
    const uint32_t sb = smem_u32(smem);
    const int tid = threadIdx.x;
    const int wid = tid >> 5;
    const int lane = tid & 31;
    const int warp_m = wid & 3;
    const int warp_n = wid >> 2;
    const int m0 = blockIdx.y * BM;
    const int n0 = blockIdx.x * BN;

    float acc[2][8][4];
#pragma unroll
    for (int mt = 0; mt < 2; ++mt)
#pragma unroll
        for (int nt = 0; nt < 8; ++nt)
#pragma unroll
            for (int e = 0; e < 4; ++e) acc[mt][nt][e] = 0.0f;

    const uint32_t a_row = (uint32_t)(warp_m * 32 + (lane & 15));
    const uint32_t a_kb = (uint32_t)(((lane >> 4) & 1) * 16);
    const uint32_t b_row = (uint32_t)(warp_n * 64 + (lane & 7));
    const uint32_t b_kb = (uint32_t)(((lane >> 3) & 1) * 16);

    gemm_issue_loads(sb, 0, 0, Ahi, Alo, Whi, Wlo, m0, n0, tid);
    CP_COMMIT();
    gemm_issue_loads(sb, 1, 1, Ahi, Alo, Whi, Wlo, m0, n0, tid);
    CP_COMMIT();

    for (int i = 0; i < NCHUNK; ++i) {
        if (i + 1 < NCHUNK) { CP_WAIT(1); } else { CP_WAIT(0); }
        __syncthreads();

        const uint32_t st = sb + (i & 1) * STAGE_BYTES;
        const uint32_t baseAhi = st + OFF_AHI + a_row * ROWB + a_kb;
        const uint32_t baseAlo = st + OFF_ALO + a_row * ROWB + a_kb;
        const uint32_t baseWhi = st + OFF_WHI + b_row * ROWB + b_kb;
        const uint32_t baseWlo = st + OFF_WLO + b_row * ROWB + b_kb;

#pragma unroll
        for (int ks = 0; ks < 2; ++ks) {
            uint32_t ahi[2][4], alo[2][4];
#pragma unroll
            for (int mt = 0; mt < 2; ++mt) {
                uint32_t ao = (uint32_t)(mt * 16 * ROWB + ks * 32);
                LDSM4(ahi[mt][0], ahi[mt][1], ahi[mt][2], ahi[mt][3], baseAhi + ao);
                LDSM4(alo[mt][0], alo[mt][1], alo[mt][2], alo[mt][3], baseAlo + ao);
            }
#pragma unroll
            for (int nt = 0; nt < 8; ++nt) {
                uint32_t bo = (uint32_t)(nt * 8 * ROWB + ks * 32);
                uint32_t whi[2], wlo[2];
                LDSM2(whi[0], whi[1], baseWhi + bo);
                LDSM2(wlo[0], wlo[1], baseWlo + bo);
                MMA_BF16(acc[0][nt], ahi[0], whi);
                MMA_BF16(acc[1][nt], ahi[1], whi);
                MMA_BF16(acc[0][nt], ahi[0], wlo);
                MMA_BF16(acc[1][nt], ahi[1], wlo);
                MMA_BF16(acc[0][nt], alo[0], whi);
                MMA_BF16(acc[1][nt], alo[1], whi);
            }
        }
        __syncthreads();

        if (i + 2 < NCHUNK) {
            gemm_issue_loads(sb, i & 1, i + 2, Ahi, Alo, Whi, Wlo, m0, n0, tid);
            CP_COMMIT();
        }
    }

    const int row_base = m0 + warp_m * 32 + (lane >> 2);
    const int col_base = n0 + warp_n * 64 + (lane & 3) * 2;
    int* cnt = fixcnt + z;
    uint32_t* list = fixlist + (size_t)z * FIX_CAP;
#pragma unroll
    for (int mt = 0; mt < 2; ++mt) {
#pragma unroll
        for (int nt = 0; nt < 8; ++nt) {
            const int col = col_base + nt * 8;
            const float bb0 = __ldg(bias + col);
            const float bb1 = __ldg(bias + col + 1);
            const int r0 = row_base + mt * 16;
            float v0 = acc[mt][nt][0] + bb0;
            float v1 = acc[mt][nt][1] + bb1;
            float v2 = acc[mt][nt][2] + bb0;
            float v3 = acc[mt][nt][3] + bb1;
            if (DO_SFN) {
                if (sfn_risky(v0)) { int ix = atomicAdd(cnt, 1); if (ix < FIX_CAP) list[ix] = ((uint32_t)r0 << 10) | col; }
                if (sfn_risky(v1)) { int ix = atomicAdd(cnt, 1); if (ix < FIX_CAP) list[ix] = ((uint32_t)r0 << 10) | (col + 1); }
                if (sfn_risky(v2)) { int ix = atomicAdd(cnt, 1); if (ix < FIX_CAP) list[ix] = ((uint32_t)(r0 + 8) << 10) | col; }
                if (sfn_risky(v3)) { int ix = atomicAdd(cnt, 1); if (ix < FIX_CAP) list[ix] = ((uint32_t)(r0 + 8) << 10) | (col + 1); }
                __nv_bfloat16* Cb = (__nv_bfloat16*)Cv;
                *(uint32_t*)(Cb + (size_t)r0 * DMODEL + col) =
                    packbf(sfn_quant(v0), sfn_quant(v1));
                *(uint32_t*)(Cb + (size_t)(r0 + 8) * DMODEL + col) =
                    packbf(sfn_quant(v2), sfn_quant(v3));
            } else {
                float* C = (float*)Cv;
                *(float2*)(C + (size_t)r0 * DMODEL + col) = make_float2(v0, v1);
                *(float2*)(C + (size_t)(r0 + 8) * DMODEL + col) = make_float2(v2, v3);
            }
        }
    }
}

// ---------------------------------------------------------------------------
// Fixup: recompute flagged elements in fp32, write exact bin as bf16.
// ---------------------------------------------------------------------------
__global__ void fixup_kernel(const float* __restrict__ X,
                             const float* __restrict__ W0, const float* __restrict__ bia0, __nv_bfloat16* __restrict__ C0,
                             const float* __restrict__ W1, const float* __restrict__ bia1, __nv_bfloat16* __restrict__ C1,
                             const float* __restrict__ W2, const float* __restrict__ bia2, __nv_bfloat16* __restrict__ C2,
                             const int* __restrict__ fixcnt, const uint32_t* __restrict__ fixlist) {
    const int z = blockIdx.y;
    const float* W;
    const float* bias;
    __nv_bfloat16* C;
    if (z == 0)      { W = W0; bias = bia0; C = C0; }
    else if (z == 1) { W = W1; bias = bia1; C = C1; }
    else             { W = W2; bias = bia2; C = C2; }

    int n = fixcnt[z];
    if (n > FIX_CAP) n = FIX_CAP;
    const uint32_t* list = fixlist + (size_t)z * FIX_CAP;

    const int lane = threadIdx.x & 31;
    const int warp = (blockIdx.x * blockDim.x + threadIdx.x) >> 5;
    const int nwarps = (gridDim.x * blockDim.x) >> 5;

    for (int e = warp; e < n; e += nwarps) {
        uint32_t u = list[e];
        int row = u >> 10;
        int col = u & 1023;
        const float* xr = X + (size_t)row * DMODEL;
        const float* wr = W + (size_t)col * DMODEL;
        float s = 0.0f;
#pragma unroll
        for (int j = 0; j < DMODEL / 32; ++j)
            s = fmaf(xr[lane + j * 32], wr[lane + j * 32], s);
#pragma unroll
        for (int o = 16; o; o >>= 1) s += __shfl_xor_sync(0xffffffffu, s, o);
        if (lane == 0)
            C[(size_t)row * DMODEL + col] = __float2bfloat16(sfn_quant(s + bias[col]));
    }
}

// ---------------------------------------------------------------------------
// Prep: per (token, head): inv_rms of q and k; q~ = q * (gq .* gk) hi/lo.
// One warp per row.
// ---------------------------------------------------------------------------
__global__ void prep_kernel(const __nv_bfloat16* __restrict__ qb,
                            const __nv_bfloat16* __restrict__ kb,
                            const float* __restrict__ gq, const float* __restrict__ gk,
                            __nv_bfloat16* __restrict__ qthi, __nv_bfloat16* __restrict__ qtlo,
                            float* __restrict__ irq, float* __restrict__ irk) {
    const int gwarp = (blockIdx.x * blockDim.x + threadIdx.x) >> 5;
    const int lane = threadIdx.x & 31;
    const int token = gwarp >> 4;
    const int h = gwarp & 15;
    const size_t base = (size_t)token * DMODEL + h * HDIM + lane * 2;

    __nv_bfloat162 q2 = *(const __nv_bfloat162*)(qb + base);
    __nv_bfloat162 k2 = *(const __nv_bfloat162*)(kb + base);
    float qx = __bfloat162float(q2.x), qy = __bfloat162float(q2.y);
    float kx = __bfloat162float(k2.x), ky = __bfloat162float(k2.y);
    float sq = qx * qx + qy * qy;
    float sk = kx * kx + ky * ky;
#pragma unroll
    for (int o = 16; o; o >>= 1) {
        sq += __shfl_xor_sync(0xffffffffu, sq, o);
        sk += __shfl_xor_sync(0xffffffffu, sk, o);
    }
    if (lane == 0) {
        irq[(size_t)h * TOKENS + token] = rsqrtf(sq * (1.0f / 64.0f) + 1e-6f);
        irk[(size_t)h * TOKENS + token] = rsqrtf(sk * (1.0f / 64.0f) + 1e-6f);
    }
    float gg0 = gq[lane * 2] * gk[lane * 2];
    float gg1 = gq[lane * 2 + 1] * gk[lane * 2 + 1];
    float t0 = qx * gg0, t1 = qy * gg1;
    float h0 = __bfloat162float(__float2bfloat16(t0));
    float h1 = __bfloat162float(__float2bfloat16(t1));
    *(uint32_t*)(qthi + base) = packbf(h0, h1);
    *(uint32_t*)(qtlo + base) = packbf(t0 - h0, t1 - h1);
}

// ---------------------------------------------------------------------------
// Flash attention, mma.sync bf16. Q tile 64 rows, 4 warps (16 rows each).
// S = qthi.K + qtlo.K (K exact bf16); scale 0.125*irq*irk in fp32;
// online softmax; O += Phi.V + Plo.V (V exact bf16).
// Smem: QHI/QLO 9216 each; K/V double buf 9216 each; irk 256 each. 55808 B.
// ---------------------------------------------------------------------------
#define AROWB 144
#define SM_QHI 0
#define SM_QLO 9216
#define SM_K   18432
#define SM_V   36864
#define SM_IRK 55296
#define ATTN_SMEM 55808

__global__ void __launch_bounds__(128, 1)
attn_mma_kernel(const __nv_bfloat16* __restrict__ qthi,
                const __nv_bfloat16* __restrict__ qtlo,
                const __nv_bfloat16* __restrict__ kb,
                const __nv_bfloat16* __restrict__ vb,
                const float* __restrict__ irqg, const float* __restrict__ irkg,
                __nv_bfloat16* __restrict__ ahi, __nv_bfloat16* __restrict__ alo) {
    extern __shared__ char smem[];
    const uint32_t sb = smem_u32(smem);
    const int tid = threadIdx.x;
    const int wid = tid >> 5;
    const int lane = tid & 31;
    const int gid = lane >> 2;
    const int tig = lane & 3;
    const int qb_ = blockIdx.x;
    const int h = blockIdx.y;
    const int b = blockIdx.z;
    const int tq = b * SEQ + qb_ * 64;

    // stage Q (hi/lo)
#pragma unroll
    for (int it = 0; it < 4; ++it) {
        int c = tid + it * 128;
        int r = c >> 3, cc = c & 7;
        size_t g = (size_t)(tq + r) * DMODEL + h * HDIM + cc * 8;
        CP16(sb + SM_QHI + r * AROWB + cc * 16, qthi + g);
        CP16(sb + SM_QLO + r * AROWB + cc * 16, qtlo + g);
    }
    CP_COMMIT();
    // prefetch K/V/irk for kb=0,1
#pragma unroll
    for (int pb = 0; pb < 2; ++pb) {
        int tk = b * SEQ + pb * 64;
#pragma unroll
        for (int it = 0; it < 4; ++it) {
            int c = tid + it * 128;
            int r = c >> 3, cc = c & 7;
            size_t g = (size_t)(tk + r) * DMODEL + h * HDIM + cc * 8;
            CP16(sb + SM_K + pb * 9216 + r * AROWB + cc * 16, kb + g);
            CP16(sb + SM_V + pb * 9216 + r * AROWB + cc * 16, vb + g);
        }
        if (tid < 16)
            CP16(sb + SM_IRK + pb * 256 + tid * 16, irkg + (size_t)h * TOKENS + tk + tid * 4);
        CP_COMMIT();
    }
    CP_WAIT(2);   // Q staged
    __syncthreads();

    // Q fragments (held in registers for the whole kernel)
    uint32_t qh[4][4], ql[4][4];
    {
        uint32_t bqh = sb + SM_QHI + (wid * 16 + (lane & 15)) * AROWB + ((lane >> 4) & 1) * 16;
        uint32_t bql = sb + SM_QLO + (wid * 16 + (lane & 15)) * AROWB + ((lane >> 4) & 1) * 16;
#pragma unroll
        for (int kc = 0; kc < 4; ++kc) {
            LDSM4(qh[kc][0], qh[kc][1], qh[kc][2], qh[kc][3], bqh + kc * 32);
            LDSM4(ql[kc][0], ql[kc][1], ql[kc][2], ql[kc][3], bql + kc * 32);
        }
    }
    const float irq0 = irqg[(size_t)h * TOKENS + tq + wid * 16 + gid];
    const float irq1 = irqg[(size_t)h * TOKENS + tq + wid * 16 + gid + 8];
    const float sc0 = 0.125f * irq0;
    const float sc1 = 0.125f * irq1;

    float m0 = -1e30f, m1 = -1e30f, l0 = 0.0f, l1 = 0.0f;
    float o[8][4];
#pragma unroll
    for (int d = 0; d < 8; ++d)
#pragma unroll
        for (int e = 0; e < 4; ++e) o[d][e] = 0.0f;

    for (int kbi = 0; kbi < SEQ / 64; ++kbi) {
        if (kbi < SEQ / 64 - 1) { CP_WAIT(1); } else { CP_WAIT(0); }
        __syncthreads();
        const int buf = kbi & 1;
        const uint32_t Kb = sb + SM_K + buf * 9216;
        const uint32_t Vb = sb + SM_V + buf * 9216;

        float2 irk2[8];
#pragma unroll
        for (int j = 0; j < 8; ++j)
            irk2[j] = *(const float2*)(smem + SM_IRK + buf * 256 + (8 * j + 2 * tig) * 4);

        // S = q~ . K
        float s[8][4];
#pragma unroll
        for (int j = 0; j < 8; ++j)
#pragma unroll
            for (int e = 0; e < 4; ++e) s[j][e] = 0.0f;
#pragma unroll
        for (int kc = 0; kc < 4; ++kc) {
#pragma unroll
            for (int j = 0; j < 8; ++j) {
                uint32_t kf[2];
                LDSM2(kf[0], kf[1],
                      Kb + (8 * j + (lane & 7)) * AROWB + ((lane >> 3) & 1) * 16 + kc * 32);
                MMA_BF16(s[j], qh[kc], kf);
                MMA_BF16(s[j], ql[kc], kf);
            }
        }

        // scale + online softmax
        float rm0 = -1e30f, rm1 = -1e30f;
#pragma unroll
        for (int j = 0; j < 8; ++j) {
            s[j][0] *= sc0 * irk2[j].x;
            s[j][1] *= sc0 * irk2[j].y;
            s[j][2] *= sc1 * irk2[j].x;
            s[j][3] *= sc1 * irk2[j].y;
            rm0 = fmaxf(rm0, fmaxf(s[j][0], s[j][1]));
            rm1 = fmaxf(rm1, fmaxf(s[j][2], s[j][3]));
        }
        rm0 = fmaxf(rm0, __shfl_xor_sync(0xffffffffu, rm0, 1));
        rm0 = fmaxf(rm0, __shfl_xor_sync(0xffffffffu, rm0, 2));
        rm1 = fmaxf(rm1, __shfl_xor_sync(0xffffffffu, rm1, 1));
        rm1 = fmaxf(rm1, __shfl_xor_sync(0xffffffffu, rm1, 2));
        const float mn0 = fmaxf(m0, rm0);
        const float mn1 = fmaxf(m1, rm1);
        const float al0 = __expf(m0 - mn0);
        const float al1 = __expf(m1 - mn1);
        m0 = mn0; m1 = mn1;
        float rs0 = 0.0f, rs1 = 0.0f;
#pragma unroll
        for (int j = 0; j < 8; ++j) {
            s[j][0] = __expf(s[j][0] - mn0);
            s[j][1] = __expf(s[j][1] - mn0);
            s[j][2] = __expf(s[j][2] - mn1);
            s[j][3] = __expf(s[j][3] - mn1);
            rs0 += s[j][0] + s[j][1];
            rs1 += s[j][2] + s[j][3];
        }
        rs0 += __shfl_xor_sync(0xffffffffu, rs0, 1);
        rs0 += __shfl_xor_sync(0xffffffffu, rs0, 2);
        rs1 += __shfl_xor_sync(0xffffffffu, rs1, 1);
        rs1 += __shfl_xor_sync(0xffffffffu, rs1, 2);
        l0 = l0 * al0 + rs0;
        l1 = l1 * al1 + rs1;
#pragma unroll
        for (int d = 0; d < 8; ++d) {
            o[d][0] *= al0; o[d][1] *= al0;
            o[d][2] *= al1; o[d][3] *= al1;
        }

        // P fragments (hi/lo) from S registers
        uint32_t pah[4][4], pal[4][4];
#pragma unroll
        for (int jj = 0; jj < 4; ++jj) {
            float p00 = s[2 * jj][0], p01 = s[2 * jj][1], p02 = s[2 * jj][2], p03 = s[2 * jj][3];
            float p10 = s[2 * jj + 1][0], p11 = s[2 * jj + 1][1], p12 = s[2 * jj + 1][2], p13 = s[2 * jj + 1][3];
            float h00 = __bfloat162float(__float2bfloat16(p00));
            float h01 = __bfloat162float(__float2bfloat16(p01));
            float h02 = __bfloat162float(__float2bfloat16(p02));
            float h03 = __bfloat162float(__float2bfloat16(p03));
            float h10 = __bfloat162float(__float2bfloat16(p10));
            float h11 = __bfloat162float(__float2bfloat16(p11));
            float h12 = __bfloat162float(__float2bfloat16(p12));
            float h13 = __bfloat162float(__float2bfloat16(p13));
            pah[jj][0] = packbf(h00, h01);
            pah[jj][1] = packbf(h02, h03);
            pah[jj][2] = packbf(h10, h11);
            pah[jj][3] = packbf(h12, h13);
            pal[jj][0] = packbf(p00 - h00, p01 - h01);
            pal[jj][1] = packbf(p02 - h02, p03 - h03);
            pal[jj][2] = packbf(p10 - h10, p11 - h11);
            pal[jj][3] = packbf(p12 - h12, p13 - h13);
        }

        // O += P . V
#pragma unroll
        for (int jj = 0; jj < 4; ++jj) {
#pragma unroll
            for (int dp = 0; dp < 4; ++dp) {
                uint32_t v0, v1, v2, v3;
                LDSM4T(v0, v1, v2, v3,
                       Vb + (jj * 16 + (lane & 15)) * AROWB + dp * 32 + ((lane >> 4) & 1) * 16);
                uint32_t vb0[2] = {v0, v1};
                uint32_t vb1[2] = {v2, v3};
                MMA_BF16(o[2 * dp], pah[jj], vb0);
                MMA_BF16(o[2 * dp], pal[jj], vb0);
                MMA_BF16(o[2 * dp + 1], pah[jj], vb1);
                MMA_BF16(o[2 * dp + 1], pal[jj], vb1);
            }
        }
        __syncthreads();

        // prefetch kbi+2
        if (kbi + 2 < SEQ / 64) {
            int tk = b * SEQ + (kbi + 2) * 64;
#pragma unroll
            for (int it = 0; it < 4; ++it) {
                int c = tid + it * 128;
                int r = c >> 3, cc = c & 7;
                size_t g = (size_t)(tk + r) * DMODEL + h * HDIM + cc * 8;
                CP16(sb + SM_K + buf * 9216 + r * AROWB + cc * 16, kb + g);
                CP16(sb + SM_V + buf * 9216 + r * AROWB + cc * 16, vb + g);
            }
            if (tid < 16)
                CP16(sb + SM_IRK + buf * 256 + tid * 16, irkg + (size_t)h * TOKENS + tk + tid * 4);
            CP_COMMIT();
        }
    }

    // epilogue: normalize, split hi/lo, store
    const float invl0 = 1.0f / l0;
    const float invl1 = 1.0f / l1;
    const int row0 = tq + wid * 16 + gid;
#pragma unroll
    for (int d = 0; d < 8; ++d) {
        const int col = h * HDIM + d * 8 + tig * 2;
        float x0 = o[d][0] * invl0, x1 = o[d][1] * invl0;
        float x2 = o[d][2] * invl1, x3 = o[d][3] * invl1;
        float h0 = __bfloat162float(__float2bfloat16(x0));
        float h1 = __bfloat162float(__float2bfloat16(x1));
        float h2 = __bfloat162float(__float2bfloat16(x2));
        float h3 = __bfloat162float(__float2bfloat16(x3));
        *(uint32_t*)(ahi + (size_t)row0 * DMODEL + col) = packbf(h0, h1);
        *(uint32_t*)(alo + (size_t)row0 * DMODEL + col) = packbf(x0 - h0, x1 - h1);
        *(uint32_t*)(ahi + (size_t)(row0 + 8) * DMODEL + col) = packbf(h2, h3);
        *(uint32_t*)(alo + (size_t)(row0 + 8) * DMODEL + col) = packbf(x2 - h2, x3 - h3);
    }
}

// ---------------------------------------------------------------------------

extern "C" void kernel_launch(void* const* d_in, const int* in_sizes, int n_in,
                              void* d_out, int out_size) {
    const float* x  = (const float*)d_in[0];
    const float* Wq = (const float*)d_in[1];
    const float* bq = (const float*)d_in[2];
    const float* Wk = (const float*)d_in[3];
    const float* bk = (const float*)d_in[4];
    const float* Wv = (const float*)d_in[5];
    const float* bv = (const float*)d_in[6];
    const float* Wo = (const float*)d_in[7];
    const float* bo = (const float*)d_in[8];
    const float* gq = (const float*)d_in[9];
    const float* gk = (const float*)d_in[10];
    float* out = (float*)d_out;

    __nv_bfloat16 *qb, *kbp, *vbp, *qthi, *qtlo, *ahi, *alo, *xhi, *xlo;
    __nv_bfloat16 *wqh, *wql, *wkh, *wkl, *wvh, *wvl, *woh, *wol;
    float *irq, *irk;
    cudaGetSymbolAddress((void**)&qb, g_qb);
    cudaGetSymbolAddress((void**)&kbp, g_kb);
    cudaGetSymbolAddress((void**)&vbp, g_vb);
    cudaGetSymbolAddress((void**)&qthi, g_qthi);
    cudaGetSymbolAddress((void**)&qtlo, g_qtlo);
    cudaGetSymbolAddress((void**)&ahi, g_ahi);
    cudaGetSymbolAddress((void**)&alo, g_alo);
    cudaGetSymbolAddress((void**)&xhi, g_xhi);
    cudaGetSymbolAddress((void**)&xlo, g_xlo);
    cudaGetSymbolAddress((void**)&wqh, g_wqhi);
    cudaGetSymbolAddress((void**)&wql, g_wqlo);
    cudaGetSymbolAddress((void**)&wkh, g_wkhi);
    cudaGetSymbolAddress((void**)&wkl, g_wklo);
    cudaGetSymbolAddress((void**)&wvh, g_wvhi);
    cudaGetSymbolAddress((void**)&wvl, g_wvlo);
    cudaGetSymbolAddress((void**)&woh, g_wohi);
    cudaGetSymbolAddress((void**)&wol, g_wolo);
    cudaGetSymbolAddress((void**)&irq, g_irq);
    cudaGetSymbolAddress((void**)&irk, g_irk);
    int* fixcnt;
    uint32_t* fixlist;
    cudaGetSymbolAddress((void**)&fixcnt, g_fixcnt);
    cudaGetSymbolAddress((void**)&fixlist, g_fixlist);

    cudaFuncSetAttribute(gemm_mma_kernel<true>,
                         cudaFuncAttributeMaxDynamicSharedMemorySize, GEMM_SMEM);
    cudaFuncSetAttribute(gemm_mma_kernel<false>,
                         cudaFuncAttributeMaxDynamicSharedMemorySize, GEMM_SMEM);
    cudaFuncSetAttribute(attn_mma_kernel,
                         cudaFuncAttributeMaxDynamicSharedMemorySize, ATTN_SMEM);

    cudaMemsetAsync(fixcnt, 0, 4 * sizeof(int));

    const int NX4 = TOKENS * DMODEL / 4;
    const int NW4 = DMODEL * DMODEL / 4;
    split_kernel<<<NX4 / 256, 256>>>(x, xhi, xlo, NX4);
    split_kernel<<<NW4 / 256, 256>>>(Wq, wqh, wql, NW4);
    split_kernel<<<NW4 / 256, 256>>>(Wk, wkh, wkl, NW4);
    split_kernel<<<NW4 / 256, 256>>>(Wv, wvh, wvl, NW4);
    split_kernel<<<NW4 / 256, 256>>>(Wo, woh, wol, NW4);

    // QKV projections -> bf16 (exact sfn values), with boundary flags
    gemm_mma_kernel<true><<<dim3(DMODEL / BN, TOKENS / BM, 3), 256, GEMM_SMEM>>>(
        xhi, xlo,
        wqh, wql, bq, qb,
        wkh, wkl, bk, kbp,
        wvh, wvl, bv, vbp,
        fixcnt, fixlist);

    fixup_kernel<<<dim3(32, 3), 256>>>(x, Wq, bq, qb, Wk, bk, kbp, Wv, bv, vbp,
                                       fixcnt, fixlist);

    prep_kernel<<<(TOKENS * NHEAD) / 8, 256>>>(qb, kbp, gq, gk, qthi, qtlo, irq, irk);

    attn_mma_kernel<<<dim3(SEQ / 64, NHEAD, BATCH), 128, ATTN_SMEM>>>(
        qthi, qtlo, kbp, vbp, irq, irk, ahi, alo);

    // O-projection (smooth; no fixup), fp32 out
    gemm_mma_kernel<false><<<dim3(DMODEL / BN, TOKENS / BM, 1), 256, GEMM_SMEM>>>(
        ahi, alo,
        woh, wol, bo, out,
        woh, wol, bo, out,
        woh, wol, bo, out,
        fixcnt + 3, fixlist);
}

// round 6
// speedup vs baseline: 3.0359x; 1.1006x over previous
#include <cuda_runtime.h>
#include <cuda_bf16.h>
#include <math.h>
#include <stdint.h>

#define TOKENS 4096      // B*L
#define SEQ    2048
#define BATCH  2
#define DMODEL 1024
#define NHEAD  16
#define HDIM   64

#define FIX_CAP (1 << 18)
#define LOG2E 1.4426950408889634f

// ---------------------------------------------------------------------------
// Scratch (__device__ globals)
// ---------------------------------------------------------------------------
__device__ __nv_bfloat16 g_qb[TOKENS * DMODEL];
__device__ __nv_bfloat16 g_kb[TOKENS * DMODEL];
__device__ __nv_bfloat16 g_vb[TOKENS * DMODEL];
__device__ __nv_bfloat16 g_qthi[TOKENS * DMODEL];
__device__ __nv_bfloat16 g_qtlo[TOKENS * DMODEL];
__device__ float g_irq[NHEAD * TOKENS];
__device__ float g_irk[NHEAD * TOKENS];

__device__ __nv_bfloat16 g_xhi[TOKENS * DMODEL];
__device__ __nv_bfloat16 g_xlo[TOKENS * DMODEL];
__device__ __nv_bfloat16 g_ahi[TOKENS * DMODEL];
__device__ __nv_bfloat16 g_alo[TOKENS * DMODEL];
__device__ __nv_bfloat16 g_wqhi[DMODEL * DMODEL];
__device__ __nv_bfloat16 g_wqlo[DMODEL * DMODEL];
__device__ __nv_bfloat16 g_wkhi[DMODEL * DMODEL];
__device__ __nv_bfloat16 g_wklo[DMODEL * DMODEL];
__device__ __nv_bfloat16 g_wvhi[DMODEL * DMODEL];
__device__ __nv_bfloat16 g_wvlo[DMODEL * DMODEL];
__device__ __nv_bfloat16 g_wohi[DMODEL * DMODEL];
__device__ __nv_bfloat16 g_wolo[DMODEL * DMODEL];

__device__ int g_fixcnt[4];          // [3] doubles as qlo-nonzero flag
__device__ uint32_t g_fixlist[3 * FIX_CAP];

// ---------------------------------------------------------------------------
// helpers
// ---------------------------------------------------------------------------
__device__ __forceinline__ uint32_t smem_u32(const void* p) {
    uint32_t a;
    asm("{ .reg .u64 t; cvta.to.shared.u64 t, %1; cvt.u32.u64 %0, t; }" : "=r"(a) : "l"(p));
    return a;
}

#define CP16(s, g)  asm volatile("cp.async.cg.shared.global [%0], [%1], 16;" :: "r"(s), "l"(g) : "memory")
#define CP_COMMIT() asm volatile("cp.async.commit_group;" ::: "memory")
#define CP_WAIT(n)  asm volatile("cp.async.wait_group %0;" :: "n"(n) : "memory")

#define LDSM4(r0, r1, r2, r3, a) \
    asm volatile("ldmatrix.sync.aligned.m8n8.x4.shared.b16 {%0,%1,%2,%3}, [%4];" \
        : "=r"(r0), "=r"(r1), "=r"(r2), "=r"(r3) : "r"(a))
#define LDSM4T(r0, r1, r2, r3, a) \
    asm volatile("ldmatrix.sync.aligned.m8n8.x4.trans.shared.b16 {%0,%1,%2,%3}, [%4];" \
        : "=r"(r0), "=r"(r1), "=r"(r2), "=r"(r3) : "r"(a))

#define MMA_BF16(d, a, b) \
    asm volatile("mma.sync.aligned.m16n8k16.row.col.f32.bf16.bf16.f32 " \
        "{%0,%1,%2,%3}, {%4,%5,%6,%7}, {%8,%9}, {%0,%1,%2,%3};" \
        : "+f"((d)[0]), "+f"((d)[1]), "+f"((d)[2]), "+f"((d)[3]) \
        : "r"((a)[0]), "r"((a)[1]), "r"((a)[2]), "r"((a)[3]), "r"((b)[0]), "r"((b)[1]))

__device__ __forceinline__ float sfn_quant(float x) {
    float t = rintf(x * 2.0f);
    t = fminf(fmaxf(t, -8.0f), 8.0f);
    return t * 0.5f;
}
__device__ __forceinline__ bool sfn_risky(float v) {
    float t = v * 2.0f;
    float d = 0.5f - fabsf(t - rintf(t));
    return (d < 1e-3f) && (fabsf(t) < 8.6f);
}
__device__ __forceinline__ uint32_t packbf(float lo, float hi) {
    __nv_bfloat162 t = __floats2bfloat162_rn(lo, hi);
    return *reinterpret_cast<uint32_t*>(&t);
}

// ---------------------------------------------------------------------------
// fp32 -> (bf16 hi, bf16 lo) split; single matrix
// ---------------------------------------------------------------------------
__device__ __forceinline__ void split_body(const float* __restrict__ X,
                                           __nv_bfloat16* __restrict__ hi,
                                           __nv_bfloat16* __restrict__ lo, int i) {
    float4 v = ((const float4*)X)[i];
    __nv_bfloat16 h0 = __float2bfloat16(v.x);
    __nv_bfloat16 h1 = __float2bfloat16(v.y);
    __nv_bfloat16 h2 = __float2bfloat16(v.z);
    __nv_bfloat16 h3 = __float2bfloat16(v.w);
    __nv_bfloat16 l0 = __float2bfloat16(v.x - __bfloat162float(h0));
    __nv_bfloat16 l1 = __float2bfloat16(v.y - __bfloat162float(h1));
    __nv_bfloat16 l2 = __float2bfloat16(v.z - __bfloat162float(h2));
    __nv_bfloat16 l3 = __float2bfloat16(v.w - __bfloat162float(h3));
    ((__nv_bfloat162*)hi)[2 * i + 0] = __halves2bfloat162(h0, h1);
    ((__nv_bfloat162*)hi)[2 * i + 1] = __halves2bfloat162(h2, h3);
    ((__nv_bfloat162*)lo)[2 * i + 0] = __halves2bfloat162(l0, l1);
    ((__nv_bfloat162*)lo)[2 * i + 1] = __halves2bfloat162(l2, l3);
}

__global__ void split_kernel(const float* __restrict__ X,
                             __nv_bfloat16* __restrict__ hi,
                             __nv_bfloat16* __restrict__ lo, int n4) {
    int i = blockIdx.x * blockDim.x + threadIdx.x;
    if (i < n4) split_body(X, hi, lo, i);
}

// fused 4-weight split (grid.y selects the matrix)
__global__ void split4_kernel(const float* __restrict__ W0, __nv_bfloat16* __restrict__ h0, __nv_bfloat16* __restrict__ l0,
                              const float* __restrict__ W1, __nv_bfloat16* __restrict__ h1, __nv_bfloat16* __restrict__ l1,
                              const float* __restrict__ W2, __nv_bfloat16* __restrict__ h2, __nv_bfloat16* __restrict__ l2,
                              const float* __restrict__ W3, __nv_bfloat16* __restrict__ h3, __nv_bfloat16* __restrict__ l3,
                              int n4) {
    int i = blockIdx.x * blockDim.x + threadIdx.x;
    if (i >= n4) return;
    const int z = blockIdx.y;
    if (z == 0)      split_body(W0, h0, l0, i);
    else if (z == 1) split_body(W1, h1, l1, i);
    else if (z == 2) split_body(W2, h2, l2, i);
    else             split_body(W3, h3, l3, i);
}

// ---------------------------------------------------------------------------
// mma.sync bf16x3 GEMM-NT. BM=128, BN=256, BK=32. 8 warps as 2m x 4n,
// warp tile 64x64. 3-stage cp.async pipeline. B fragments via LDSM4 pairs.
// ---------------------------------------------------------------------------
#define BM 128
#define BN 256
#define BK 32
#define NCHUNK (DMODEL / BK)     // 32
#define ROWB 80
#define OFF_AHI 0
#define OFF_ALO 10240
#define OFF_WHI 20480
#define OFF_WLO 40960
#define STAGE_BYTES 61440
#define NSTAGE 3
#define GEMM_SMEM (NSTAGE * STAGE_BYTES)   // 184320

__device__ __forceinline__ void gemm_issue_loads(
    uint32_t sb, int buf, int chunk,
    const __nv_bfloat16* __restrict__ Ahi, const __nv_bfloat16* __restrict__ Alo,
    const __nv_bfloat16* __restrict__ Whi, const __nv_bfloat16* __restrict__ Wlo,
    int m0, int n0, int tid) {
    const uint32_t b = sb + buf * STAGE_BYTES;
    const int k0 = chunk * BK;
    // A: 128 rows x 4 16B-chunks = 512 slots
#pragma unroll
    for (int j = 0; j < 2; ++j) {
        int slot = tid + j * 256;
        int r = slot >> 2, c = slot & 3;
        uint32_t so = (uint32_t)(r * ROWB + c * 16);
        size_t ga = (size_t)(m0 + r) * DMODEL + k0 + c * 8;
        CP16(b + OFF_AHI + so, Ahi + ga);
        CP16(b + OFF_ALO + so, Alo + ga);
    }
    // W: 256 rows x 4 = 1024 slots
#pragma unroll
    for (int j = 0; j < 4; ++j) {
        int slot = tid + j * 256;
        int r = slot >> 2, c = slot & 3;
        uint32_t so = (uint32_t)(r * ROWB + c * 16);
        size_t gw = (size_t)(n0 + r) * DMODEL + k0 + c * 8;
        CP16(b + OFF_WHI + so, Whi + gw);
        CP16(b + OFF_WLO + so, Wlo + gw);
    }
}

template <bool DO_SFN>
__global__ void __launch_bounds__(256, 1)
gemm_mma_kernel(const __nv_bfloat16* __restrict__ Ahi, const __nv_bfloat16* __restrict__ Alo,
                const __nv_bfloat16* __restrict__ W0h, const __nv_bfloat16* __restrict__ W0l,
                const float* __restrict__ b0, void* __restrict__ C0v,
                const __nv_bfloat16* __restrict__ W1h, const __nv_bfloat16* __restrict__ W1l,
                const float* __restrict__ b1, void* __restrict__ C1v,
                const __nv_bfloat16* __restrict__ W2h, const __nv_bfloat16* __restrict__ W2l,
                const float* __restrict__ b2, void* __restrict__ C2v,
                int* __restrict__ fixcnt, uint32_t* __restrict__ fixlist) {
    const __nv_bfloat16 *Whi, *Wlo;
    const float* bias;
    void* Cv;
    const int z = blockIdx.z;
    if (z == 0)      { Whi = W0h; Wlo = W0l; bias = b0; Cv = C0v; }
    else if (z == 1) { Whi = W1h; Wlo = W1l; bias = b1; Cv = C1v; }
    else             { Whi = W2h; Wlo = W2l; bias = b2; Cv = C2v; }

    extern __shared__ char smem[];
    const uint32_t sb = smem_u32(smem);
    const int tid = threadIdx.x;
    const int wid = tid >> 5;
    const int lane = tid & 31;
    const int warp_m = wid & 1;      // 2 m-slices of 64 rows
    const int warp_n = wid >> 1;     // 4 n-slices of 64 cols
    const int m0 = blockIdx.y * BM;
    const int n0 = blockIdx.x * BN;

    float acc[4][8][4];
#pragma unroll
    for (int mt = 0; mt < 4; ++mt)
#pragma unroll
        for (int nt = 0; nt < 8; ++nt)
#pragma unroll
            for (int e = 0; e < 4; ++e) acc[mt][nt][e] = 0.0f;

    // A fragment address: row = warp_m*64 + mt*16 + (lane&15), kb = bit4*16
    const uint32_t a_off = (uint32_t)((warp_m * 64 + (lane & 15)) * ROWB
                                      + ((lane >> 4) & 1) * 16);
    // B fragment (LDSM4 pair): row = warp_n*64 + ntp*16 + bit4*8 + (lane&7), kb = bit3*16
    const uint32_t b_off = (uint32_t)((warp_n * 64 + ((lane >> 4) & 1) * 8 + (lane & 7)) * ROWB
                                      + ((lane >> 3) & 1) * 16);

    gemm_issue_loads(sb, 0, 0, Ahi, Alo, Whi, Wlo, m0, n0, tid); CP_COMMIT();
    gemm_issue_loads(sb, 1, 1, Ahi, Alo, Whi, Wlo, m0, n0, tid); CP_COMMIT();
    gemm_issue_loads(sb, 2, 2, Ahi, Alo, Whi, Wlo, m0, n0, tid); CP_COMMIT();

    int buf = 0;
    for (int i = 0; i < NCHUNK; ++i) {
        if (i + 2 < NCHUNK) { CP_WAIT(2); } else if (i + 1 < NCHUNK) { CP_WAIT(1); } else { CP_WAIT(0); }
        __syncthreads();

        const uint32_t st = sb + buf * STAGE_BYTES;
#pragma unroll
        for (int ks = 0; ks < 2; ++ks) {
            uint32_t ah[4][4], al[4][4];
#pragma unroll
            for (int mt = 0; mt < 4; ++mt) {
                uint32_t ao = a_off + (uint32_t)(mt * 16 * ROWB + ks * 32);
                LDSM4(ah[mt][0], ah[mt][1], ah[mt][2], ah[mt][3], st + OFF_AHI + ao);
                LDSM4(al[mt][0], al[mt][1], al[mt][2], al[mt][3], st + OFF_ALO + ao);
            }
#pragma unroll
            for (int ntp = 0; ntp < 4; ++ntp) {
                uint32_t bo = b_off + (uint32_t)(ntp * 16 * ROWB + ks * 32);
                uint32_t wh[4], wl[4];
                LDSM4(wh[0], wh[1], wh[2], wh[3], st + OFF_WHI + bo);
                LDSM4(wl[0], wl[1], wl[2], wl[3], st + OFF_WLO + bo);
                uint32_t bh0[2] = {wh[0], wh[1]};
                uint32_t bh1[2] = {wh[2], wh[3]};
                uint32_t bl0[2] = {wl[0], wl[1]};
                uint32_t bl1[2] = {wl[2], wl[3]};
#pragma unroll
                for (int mt = 0; mt < 4; ++mt) {
                    MMA_BF16(acc[mt][2 * ntp],     ah[mt], bh0);
                    MMA_BF16(acc[mt][2 * ntp],     ah[mt], bl0);
                    MMA_BF16(acc[mt][2 * ntp],     al[mt], bh0);
                    MMA_BF16(acc[mt][2 * ntp + 1], ah[mt], bh1);
                    MMA_BF16(acc[mt][2 * ntp + 1], ah[mt], bl1);
                    MMA_BF16(acc[mt][2 * ntp + 1], al[mt], bh1);
                }
            }
        }
        __syncthreads();

        if (i + 3 < NCHUNK) {
            gemm_issue_loads(sb, buf, i + 3, Ahi, Alo, Whi, Wlo, m0, n0, tid);
            CP_COMMIT();
        }
        if (++buf == NSTAGE) buf = 0;
    }

    // Epilogue
    const int col_base = n0 + warp_n * 64 + (lane & 3) * 2;
    int* cnt = fixcnt + z;
    uint32_t* list = fixlist + (size_t)z * FIX_CAP;
#pragma unroll
    for (int mt = 0; mt < 4; ++mt) {
        const int row_base = m0 + warp_m * 64 + mt * 16 + (lane >> 2);
#pragma unroll
        for (int nt = 0; nt < 8; ++nt) {
            const int col = col_base + nt * 8;
            const float bb0 = __ldg(bias + col);
            const float bb1 = __ldg(bias + col + 1);
            const int r0 = row_base;
            float v0 = acc[mt][nt][0] + bb0;
            float v1 = acc[mt][nt][1] + bb1;
            float v2 = acc[mt][nt][2] + bb0;
            float v3 = acc[mt][nt][3] + bb1;
            if (DO_SFN) {
                if (sfn_risky(v0)) { int ix = atomicAdd(cnt, 1); if (ix < FIX_CAP) list[ix] = ((uint32_t)r0 << 10) | col; }
                if (sfn_risky(v1)) { int ix = atomicAdd(cnt, 1); if (ix < FIX_CAP) list[ix] = ((uint32_t)r0 << 10) | (col + 1); }
                if (sfn_risky(v2)) { int ix = atomicAdd(cnt, 1); if (ix < FIX_CAP) list[ix] = ((uint32_t)(r0 + 8) << 10) | col; }
                if (sfn_risky(v3)) { int ix = atomicAdd(cnt, 1); if (ix < FIX_CAP) list[ix] = ((uint32_t)(r0 + 8) << 10) | (col + 1); }
                __nv_bfloat16* Cb = (__nv_bfloat16*)Cv;
                *(uint32_t*)(Cb + (size_t)r0 * DMODEL + col) = packbf(sfn_quant(v0), sfn_quant(v1));
                *(uint32_t*)(Cb + (size_t)(r0 + 8) * DMODEL + col) = packbf(sfn_quant(v2), sfn_quant(v3));
            } else {
                float* C = (float*)Cv;
                *(float2*)(C + (size_t)r0 * DMODEL + col) = make_float2(v0, v1);
                *(float2*)(C + (size_t)(r0 + 8) * DMODEL + col) = make_float2(v2, v3);
            }
        }
    }
}

// ---------------------------------------------------------------------------
// Fixup (unchanged)
// ---------------------------------------------------------------------------
__global__ void fixup_kernel(const float* __restrict__ X,
                             const float* __restrict__ W0, const float* __restrict__ bia0, __nv_bfloat16* __restrict__ C0,
                             const float* __restrict__ W1, const float* __restrict__ bia1, __nv_bfloat16* __restrict__ C1,
                             const float* __restrict__ W2, const float* __restrict__ bia2, __nv_bfloat16* __restrict__ C2,
                             const int* __restrict__ fixcnt, const uint32_t* __restrict__ fixlist) {
    const int z = blockIdx.y;
    const float* W;
    const float* bias;
    __nv_bfloat16* C;
    if (z == 0)      { W = W0; bias = bia0; C = C0; }
    else if (z == 1) { W = W1; bias = bia1; C = C1; }
    else             { W = W2; bias = bia2; C = C2; }

    int n = fixcnt[z];
    if (n > FIX_CAP) n = FIX_CAP;
    const uint32_t* list = fixlist + (size_t)z * FIX_CAP;

    const int lane = threadIdx.x & 31;
    const int warp = (blockIdx.x * blockDim.x + threadIdx.x) >> 5;
    const int nwarps = (gridDim.x * blockDim.x) >> 5;

    for (int e = warp; e < n; e += nwarps) {
        uint32_t u = list[e];
        int row = u >> 10;
        int col = u & 1023;
        const float* xr = X + (size_t)row * DMODEL;
        const float* wr = W + (size_t)col * DMODEL;
        float s = 0.0f;
#pragma unroll
        for (int j = 0; j < DMODEL / 32; ++j)
            s = fmaf(xr[lane + j * 32], wr[lane + j * 32], s);
#pragma unroll
        for (int o = 16; o; o >>= 1) s += __shfl_xor_sync(0xffffffffu, s, o);
        if (lane == 0)
            C[(size_t)row * DMODEL + col] = __float2bfloat16(sfn_quant(s + bias[col]));
    }
}

// ---------------------------------------------------------------------------
// Prep: irq/irk, q~ hi/lo, and qlo-nonzero flag.
// ---------------------------------------------------------------------------
__global__ void prep_kernel(const __nv_bfloat16* __restrict__ qb,
                            const __nv_bfloat16* __restrict__ kb,
                            const float* __restrict__ gq, const float* __restrict__ gk,
                            __nv_bfloat16* __restrict__ qthi, __nv_bfloat16* __restrict__ qtlo,
                            float* __restrict__ irq, float* __restrict__ irk,
                            int* __restrict__ qlo_flag) {
    const int gwarp = (blockIdx.x * blockDim.x + threadIdx.x) >> 5;
    const int lane = threadIdx.x & 31;
    const int token = gwarp >> 4;
    const int h = gwarp & 15;
    const size_t base = (size_t)token * DMODEL + h * HDIM + lane * 2;

    __nv_bfloat162 q2 = *(const __nv_bfloat162*)(qb + base);
    __nv_bfloat162 k2 = *(const __nv_bfloat162*)(kb + base);
    float qx = __bfloat162float(q2.x), qy = __bfloat162float(q2.y);
    float kx = __bfloat162float(k2.x), ky = __bfloat162float(k2.y);
    float sq = qx * qx + qy * qy;
    float sk = kx * kx + ky * ky;
#pragma unroll
    for (int o = 16; o; o >>= 1) {
        sq += __shfl_xor_sync(0xffffffffu, sq, o);
        sk += __shfl_xor_sync(0xffffffffu, sk, o);
    }
    if (lane == 0) {
        irq[(size_t)h * TOKENS + token] = rsqrtf(sq * (1.0f / 64.0f) + 1e-6f);
        irk[(size_t)h * TOKENS + token] = rsqrtf(sk * (1.0f / 64.0f) + 1e-6f);
    }
    float gg0 = gq[lane * 2] * gk[lane * 2];
    float gg1 = gq[lane * 2 + 1] * gk[lane * 2 + 1];
    float t0 = qx * gg0, t1 = qy * gg1;
    float h0 = __bfloat162float(__float2bfloat16(t0));
    float h1 = __bfloat162float(__float2bfloat16(t1));
    uint32_t lopack = packbf(t0 - h0, t1 - h1);
    *(uint32_t*)(qthi + base) = packbf(h0, h1);
    *(uint32_t*)(qtlo + base) = lopack;
    if (__any_sync(0xffffffffu, lopack != 0u)) {
        if (lane == 0) atomicOr(qlo_flag, 1);
    }
}

// ---------------------------------------------------------------------------
// Flash attention, mma.sync bf16. log2-domain softmax; optional ql stream.
// ---------------------------------------------------------------------------
#define AROWB 144
#define SM_QHI 0
#define SM_QLO 9216
#define SM_K   18432
#define SM_V   36864
#define SM_IRK 55296
#define ATTN_SMEM 55808

__global__ void __launch_bounds__(128, 1)
attn_mma_kernel(const __nv_bfloat16* __restrict__ qthi,
                const __nv_bfloat16* __restrict__ qtlo,
                const __nv_bfloat16* __restrict__ kb,
                const __nv_bfloat16* __restrict__ vb,
                const float* __restrict__ irqg, const float* __restrict__ irkg,
                const int* __restrict__ qlo_flag,
                __nv_bfloat16* __restrict__ ahi, __nv_bfloat16* __restrict__ alo) {
    extern __shared__ char smem[];
    const uint32_t sb = smem_u32(smem);
    const int tid = threadIdx.x;
    const int wid = tid >> 5;
    const int lane = tid & 31;
    const int gid = lane >> 2;
    const int tig = lane & 3;
    const int qb_ = blockIdx.x;
    const int h = blockIdx.y;
    const int b = blockIdx.z;
    const int tq = b * SEQ + qb_ * 64;
    const int qlnz = *qlo_flag;

    // stage Q hi (and lo only if needed)
#pragma unroll
    for (int it = 0; it < 4; ++it) {
        int c = tid + it * 128;
        int r = c >> 3, cc = c & 7;
        size_t g = (size_t)(tq + r) * DMODEL + h * HDIM + cc * 8;
        CP16(sb + SM_QHI + r * AROWB + cc * 16, qthi + g);
        if (qlnz) CP16(sb + SM_QLO + r * AROWB + cc * 16, qtlo + g);
    }
    CP_COMMIT();
#pragma unroll
    for (int pb = 0; pb < 2; ++pb) {
        int tk = b * SEQ + pb * 64;
#pragma unroll
        for (int it = 0; it < 4; ++it) {
            int c = tid + it * 128;
            int r = c >> 3, cc = c & 7;
            size_t g = (size_t)(tk + r) * DMODEL + h * HDIM + cc * 8;
            CP16(sb + SM_K + pb * 9216 + r * AROWB + cc * 16, kb + g);
            CP16(sb + SM_V + pb * 9216 + r * AROWB + cc * 16, vb + g);
        }
        if (tid < 16)
            CP16(sb + SM_IRK + pb * 256 + tid * 16, irkg + (size_t)h * TOKENS + tk + tid * 4);
        CP_COMMIT();
    }
    CP_WAIT(2);
    __syncthreads();

    uint32_t qh[4][4], ql[4][4];
    {
        uint32_t bqh = sb + SM_QHI + (wid * 16 + (lane & 15)) * AROWB + ((lane >> 4) & 1) * 16;
        uint32_t bql = sb + SM_QLO + (wid * 16 + (lane & 15)) * AROWB + ((lane >> 4) & 1) * 16;
#pragma unroll
        for (int kc = 0; kc < 4; ++kc) {
            LDSM4(qh[kc][0], qh[kc][1], qh[kc][2], qh[kc][3], bqh + kc * 32);
            if (qlnz) LDSM4(ql[kc][0], ql[kc][1], ql[kc][2], ql[kc][3], bql + kc * 32);
        }
    }
    const float irq0 = irqg[(size_t)h * TOKENS + tq + wid * 16 + gid];
    const float irq1 = irqg[(size_t)h * TOKENS + tq + wid * 16 + gid + 8];
    const float sc0 = 0.125f * LOG2E * irq0;   // log2-domain scale
    const float sc1 = 0.125f * LOG2E * irq1;

    // K fragment base (LDSM4 pair over two 8-row j tiles)
    const uint32_t kf_off = (uint32_t)((((lane >> 4) & 1) * 8 + (lane & 7)) * AROWB
                                       + ((lane >> 3) & 1) * 16);

    float m0 = -1e30f, m1 = -1e30f, l0 = 0.0f, l1 = 0.0f;
    float o[8][4];
#pragma unroll
    for (int d = 0; d < 8; ++d)
#pragma unroll
        for (int e = 0; e < 4; ++e) o[d][e] = 0.0f;

    for (int kbi = 0; kbi < SEQ / 64; ++kbi) {
        if (kbi < SEQ / 64 - 1) { CP_WAIT(1); } else { CP_WAIT(0); }
        __syncthreads();
        const int buf = kbi & 1;
        const uint32_t Kb = sb + SM_K + buf * 9216;
        const uint32_t Vb = sb + SM_V + buf * 9216;

        float2 irk2[8];
#pragma unroll
        for (int j = 0; j < 8; ++j)
            irk2[j] = *(const float2*)(smem + SM_IRK + buf * 256 + (8 * j + 2 * tig) * 4);

        float s[8][4];
#pragma unroll
        for (int j = 0; j < 8; ++j)
#pragma unroll
            for (int e = 0; e < 4; ++e) s[j][e] = 0.0f;

        if (qlnz) {
#pragma unroll
            for (int kc = 0; kc < 4; ++kc) {
#pragma unroll
                for (int jp = 0; jp < 4; ++jp) {
                    uint32_t kf[4];
                    LDSM4(kf[0], kf[1], kf[2], kf[3], Kb + kf_off + jp * 16 * AROWB + kc * 32);
                    uint32_t f0[2] = {kf[0], kf[1]};
                    uint32_t f1[2] = {kf[2], kf[3]};
                    MMA_BF16(s[2 * jp], qh[kc], f0);
                    MMA_BF16(s[2 * jp], ql[kc], f0);
                    MMA_BF16(s[2 * jp + 1], qh[kc], f1);
                    MMA_BF16(s[2 * jp + 1], ql[kc], f1);
                }
            }
        } else {
#pragma unroll
            for (int kc = 0; kc < 4; ++kc) {
#pragma unroll
                for (int jp = 0; jp < 4; ++jp) {
                    uint32_t kf[4];
                    LDSM4(kf[0], kf[1], kf[2], kf[3], Kb + kf_off + jp * 16 * AROWB + kc * 32);
                    uint32_t f0[2] = {kf[0], kf[1]};
                    uint32_t f1[2] = {kf[2], kf[3]};
                    MMA_BF16(s[2 * jp], qh[kc], f0);
                    MMA_BF16(s[2 * jp + 1], qh[kc], f1);
                }
            }
        }

        // scale (log2 domain) + online softmax via exp2
        float rm0 = -1e30f, rm1 = -1e30f;
#pragma unroll
        for (int j = 0; j < 8; ++j) {
            s[j][0] *= sc0 * irk2[j].x;
            s[j][1] *= sc0 * irk2[j].y;
            s[j][2] *= sc1 * irk2[j].x;
            s[j][3] *= sc1 * irk2[j].y;
            rm0 = fmaxf(rm0, fmaxf(s[j][0], s[j][1]));
            rm1 = fmaxf(rm1, fmaxf(s[j][2], s[j][3]));
        }
        rm0 = fmaxf(rm0, __shfl_xor_sync(0xffffffffu, rm0, 1));
        rm0 = fmaxf(rm0, __shfl_xor_sync(0xffffffffu, rm0, 2));
        rm1 = fmaxf(rm1, __shfl_xor_sync(0xffffffffu, rm1, 1));
        rm1 = fmaxf(rm1, __shfl_xor_sync(0xffffffffu, rm1, 2));
        const float mn0 = fmaxf(m0, rm0);
        const float mn1 = fmaxf(m1, rm1);
        const float al0 = exp2f(m0 - mn0);
        const float al1 = exp2f(m1 - mn1);
        m0 = mn0; m1 = mn1;
        float rs0 = 0.0f, rs1 = 0.0f;
#pragma unroll
        for (int j = 0; j < 8; ++j) {
            s[j][0] = exp2f(s[j][0] - mn0);
            s[j][1] = exp2f(s[j][1] - mn0);
            s[j][2] = exp2f(s[j][2] - mn1);
            s[j][3] = exp2f(s[j][3] - mn1);
            rs0 += s[j][0] + s[j][1];
            rs1 += s[j][2] + s[j][3];
        }
        rs0 += __shfl_xor_sync(0xffffffffu, rs0, 1);
        rs0 += __shfl_xor_sync(0xffffffffu, rs0, 2);
        rs1 += __shfl_xor_sync(0xffffffffu, rs1, 1);
        rs1 += __shfl_xor_sync(0xffffffffu, rs1, 2);
        l0 = l0 * al0 + rs0;
        l1 = l1 * al1 + rs1;
#pragma unroll
        for (int d = 0; d < 8; ++d) {
            o[d][0] *= al0; o[d][1] *= al0;
            o[d][2] *= al1; o[d][3] *= al1;
        }

        // P hi/lo fragments
        uint32_t pah[4][4], pal[4][4];
#pragma unroll
        for (int jj = 0; jj < 4; ++jj) {
            float p00 = s[2 * jj][0], p01 = s[2 * jj][1], p02 = s[2 * jj][2], p03 = s[2 * jj][3];
            float p10 = s[2 * jj + 1][0], p11 = s[2 * jj + 1][1], p12 = s[2 * jj + 1][2], p13 = s[2 * jj + 1][3];
            float h00 = __bfloat162float(__float2bfloat16(p00));
            float h01 = __bfloat162float(__float2bfloat16(p01));
            float h02 = __bfloat162float(__float2bfloat16(p02));
            float h03 = __bfloat162float(__float2bfloat16(p03));
            float h10 = __bfloat162float(__float2bfloat16(p10));
            float h11 = __bfloat162float(__float2bfloat16(p11));
            float h12 = __bfloat162float(__float2bfloat16(p12));
            float h13 = __bfloat162float(__float2bfloat16(p13));
            pah[jj][0] = packbf(h00, h01);
            pah[jj][1] = packbf(h02, h03);
            pah[jj][2] = packbf(h10, h11);
            pah[jj][3] = packbf(h12, h13);
            pal[jj][0] = packbf(p00 - h00, p01 - h01);
            pal[jj][1] = packbf(p02 - h02, p03 - h03);
            pal[jj][2] = packbf(p10 - h10, p11 - h11);
            pal[jj][3] = packbf(p12 - h12, p13 - h13);
        }

        // O += P . V
#pragma unroll
        for (int jj = 0; jj < 4; ++jj) {
#pragma unroll
            for (int dp = 0; dp < 4; ++dp) {
                uint32_t v0, v1, v2, v3;
                LDSM4T(v0, v1, v2, v3,
                       Vb + (jj * 16 + (lane & 15)) * AROWB + dp * 32 + ((lane >> 4) & 1) * 16);
                uint32_t vb0[2] = {v0, v1};
                uint32_t vb1[2] = {v2, v3};
                MMA_BF16(o[2 * dp], pah[jj], vb0);
                MMA_BF16(o[2 * dp], pal[jj], vb0);
                MMA_BF16(o[2 * dp + 1], pah[jj], vb1);
                MMA_BF16(o[2 * dp + 1], pal[jj], vb1);
            }
        }
        __syncthreads();

        if (kbi + 2 < SEQ / 64) {
            int tk = b * SEQ + (kbi + 2) * 64;
#pragma unroll
            for (int it = 0; it < 4; ++it) {
                int c = tid + it * 128;
                int r = c >> 3, cc = c & 7;
                size_t g = (size_t)(tk + r) * DMODEL + h * HDIM + cc * 8;
                CP16(sb + SM_K + buf * 9216 + r * AROWB + cc * 16, kb + g);
                CP16(sb + SM_V + buf * 9216 + r * AROWB + cc * 16, vb + g);
            }
            if (tid < 16)
                CP16(sb + SM_IRK + buf * 256 + tid * 16, irkg + (size_t)h * TOKENS + tk + tid * 4);
            CP_COMMIT();
        }
    }

    const float invl0 = 1.0f / l0;
    const float invl1 = 1.0f / l1;
    const int row0 = tq + wid * 16 + gid;
#pragma unroll
    for (int d = 0; d < 8; ++d) {
        const int col = h * HDIM + d * 8 + tig * 2;
        float x0 = o[d][0] * invl0, x1 = o[d][1] * invl0;
        float x2 = o[d][2] * invl1, x3 = o[d][3] * invl1;
        float h0 = __bfloat162float(__float2bfloat16(x0));
        float h1 = __bfloat162float(__float2bfloat16(x1));
        float h2 = __bfloat162float(__float2bfloat16(x2));
        float h3 = __bfloat162float(__float2bfloat16(x3));
        *(uint32_t*)(ahi + (size_t)row0 * DMODEL + col) = packbf(h0, h1);
        *(uint32_t*)(alo + (size_t)row0 * DMODEL + col) = packbf(x0 - h0, x1 - h1);
        *(uint32_t*)(ahi + (size_t)(row0 + 8) * DMODEL + col) = packbf(h2, h3);
        *(uint32_t*)(alo + (size_t)(row0 + 8) * DMODEL + col) = packbf(x2 - h2, x3 - h3);
    }
}

// ---------------------------------------------------------------------------

extern "C" void kernel_launch(void* const* d_in, const int* in_sizes, int n_in,
                              void* d_out, int out_size) {
    const float* x  = (const float*)d_in[0];
    const float* Wq = (const float*)d_in[1];
    const float* bq = (const float*)d_in[2];
    const float* Wk = (const float*)d_in[3];
    const float* bk = (const float*)d_in[4];
    const float* Wv = (const float*)d_in[5];
    const float* bv = (const float*)d_in[6];
    const float* Wo = (const float*)d_in[7];
    const float* bo = (const float*)d_in[8];
    const float* gq = (const float*)d_in[9];
    const float* gk = (const float*)d_in[10];
    float* out = (float*)d_out;

    __nv_bfloat16 *qb, *kbp, *vbp, *qthi, *qtlo, *ahi, *alo, *xhi, *xlo;
    __nv_bfloat16 *wqh, *wql, *wkh, *wkl, *wvh, *wvl, *woh, *wol;
    float *irq, *irk;
    cudaGetSymbolAddress((void**)&qb, g_qb);
    cudaGetSymbolAddress((void**)&kbp, g_kb);
    cudaGetSymbolAddress((void**)&vbp, g_vb);
    cudaGetSymbolAddress((void**)&qthi, g_qthi);
    cudaGetSymbolAddress((void**)&qtlo, g_qtlo);
    cudaGetSymbolAddress((void**)&ahi, g_ahi);
    cudaGetSymbolAddress((void**)&alo, g_alo);
    cudaGetSymbolAddress((void**)&xhi, g_xhi);
    cudaGetSymbolAddress((void**)&xlo, g_xlo);
    cudaGetSymbolAddress((void**)&wqh, g_wqhi);
    cudaGetSymbolAddress((void**)&wql, g_wqlo);
    cudaGetSymbolAddress((void**)&wkh, g_wkhi);
    cudaGetSymbolAddress((void**)&wkl, g_wklo);
    cudaGetSymbolAddress((void**)&wvh, g_wvhi);
    cudaGetSymbolAddress((void**)&wvl, g_wvlo);
    cudaGetSymbolAddress((void**)&woh, g_wohi);
    cudaGetSymbolAddress((void**)&wol, g_wolo);
    cudaGetSymbolAddress((void**)&irq, g_irq);
    cudaGetSymbolAddress((void**)&irk, g_irk);
    int* fixcnt;
    uint32_t* fixlist;
    cudaGetSymbolAddress((void**)&fixcnt, g_fixcnt);
    cudaGetSymbolAddress((void**)&fixlist, g_fixlist);

    cudaFuncSetAttribute(gemm_mma_kernel<true>,
                         cudaFuncAttributeMaxDynamicSharedMemorySize, GEMM_SMEM);
    cudaFuncSetAttribute(gemm_mma_kernel<false>,
                         cudaFuncAttributeMaxDynamicSharedMemorySize, GEMM_SMEM);
    cudaFuncSetAttribute(attn_mma_kernel,
                         cudaFuncAttributeMaxDynamicSharedMemorySize, ATTN_SMEM);

    cudaMemsetAsync(fixcnt, 0, 4 * sizeof(int));   // [3] = qlo flag

    const int NX4 = TOKENS * DMODEL / 4;
    const int NW4 = DMODEL * DMODEL / 4;
    split_kernel<<<NX4 / 256, 256>>>(x, xhi, xlo, NX4);
    split4_kernel<<<dim3(NW4 / 256, 4), 256>>>(Wq, wqh, wql, Wk, wkh, wkl,
                                               Wv, wvh, wvl, Wo, woh, wol, NW4);

    gemm_mma_kernel<true><<<dim3(DMODEL / BN, TOKENS / BM, 3), 256, GEMM_SMEM>>>(
        xhi, xlo,
        wqh, wql, bq, qb,
        wkh, wkl, bk, kbp,
        wvh, wvl, bv, vbp,
        fixcnt, fixlist);

    fixup_kernel<<<dim3(32, 3), 256>>>(x, Wq, bq, qb, Wk, bk, kbp, Wv, bv, vbp,
                                       fixcnt, fixlist);

    prep_kernel<<<(TOKENS * NHEAD) / 8, 256>>>(qb, kbp, gq, gk, qthi, qtlo,
                                               irq, irk, fixcnt + 3);

    attn_mma_kernel<<<dim3(SEQ / 64, NHEAD, BATCH), 128, ATTN_SMEM>>>(
        qthi, qtlo, kbp, vbp, irq, irk, fixcnt + 3, ahi, alo);

    gemm_mma_kernel<false><<<dim3(DMODEL / BN, TOKENS / BM, 1), 256, GEMM_SMEM>>>(
        ahi, alo,
        woh, wol, bo, out,
        woh, wol, bo, out,
        woh, wol, bo, out,
        fixcnt + 3, fixlist);
}

// round 7
// speedup vs baseline: 3.7446x; 1.2334x over previous
#include <cuda_runtime.h>
#include <cuda_bf16.h>
#include <math.h>
#include <stdint.h>

#define TOKENS 4096      // B*L
#define SEQ    2048
#define BATCH  2
#define DMODEL 1024
#define NHEAD  16
#define HDIM   64

#define FIX_CAP (1 << 18)
#define LOG2E 1.4426950408889634f

// ---------------------------------------------------------------------------
// Scratch (__device__ globals)
// ---------------------------------------------------------------------------
__device__ __nv_bfloat16 g_qb[TOKENS * DMODEL];
__device__ __nv_bfloat16 g_kb[TOKENS * DMODEL];
__device__ __nv_bfloat16 g_vb[TOKENS * DMODEL];
__device__ __nv_bfloat16 g_qthi[TOKENS * DMODEL];
__device__ __nv_bfloat16 g_qtlo[TOKENS * DMODEL];
__device__ float g_irq[NHEAD * TOKENS];
__device__ float g_irk[NHEAD * TOKENS];

__device__ __nv_bfloat16 g_xhi[TOKENS * DMODEL];
__device__ __nv_bfloat16 g_xlo[TOKENS * DMODEL];
__device__ __nv_bfloat16 g_ahi[TOKENS * DMODEL];
__device__ __nv_bfloat16 g_alo[TOKENS * DMODEL];
__device__ __nv_bfloat16 g_wqhi[DMODEL * DMODEL];
__device__ __nv_bfloat16 g_wqlo[DMODEL * DMODEL];
__device__ __nv_bfloat16 g_wkhi[DMODEL * DMODEL];
__device__ __nv_bfloat16 g_wklo[DMODEL * DMODEL];
__device__ __nv_bfloat16 g_wvhi[DMODEL * DMODEL];
__device__ __nv_bfloat16 g_wvlo[DMODEL * DMODEL];
__device__ __nv_bfloat16 g_wohi[DMODEL * DMODEL];
__device__ __nv_bfloat16 g_wolo[DMODEL * DMODEL];

__device__ int g_fixcnt[4];          // [3] doubles as qlo-nonzero flag
__device__ uint32_t g_fixlist[3 * FIX_CAP];

// ---------------------------------------------------------------------------
// helpers
// ---------------------------------------------------------------------------
__device__ __forceinline__ uint32_t smem_u32(const void* p) {
    uint32_t a;
    asm("{ .reg .u64 t; cvta.to.shared.u64 t, %1; cvt.u32.u64 %0, t; }" : "=r"(a) : "l"(p));
    return a;
}

#define CP16(s, g)  asm volatile("cp.async.cg.shared.global [%0], [%1], 16;" :: "r"(s), "l"(g) : "memory")
#define CP_COMMIT() asm volatile("cp.async.commit_group;" ::: "memory")
#define CP_WAIT(n)  asm volatile("cp.async.wait_group %0;" :: "n"(n) : "memory")

#define LDSM4(r0, r1, r2, r3, a) \
    asm volatile("ldmatrix.sync.aligned.m8n8.x4.shared.b16 {%0,%1,%2,%3}, [%4];" \
        : "=r"(r0), "=r"(r1), "=r"(r2), "=r"(r3) : "r"(a))
#define LDSM4T(r0, r1, r2, r3, a) \
    asm volatile("ldmatrix.sync.aligned.m8n8.x4.trans.shared.b16 {%0,%1,%2,%3}, [%4];" \
        : "=r"(r0), "=r"(r1), "=r"(r2), "=r"(r3) : "r"(a))

#define MMA_BF16(d, a, b) \
    asm volatile("mma.sync.aligned.m16n8k16.row.col.f32.bf16.bf16.f32 " \
        "{%0,%1,%2,%3}, {%4,%5,%6,%7}, {%8,%9}, {%0,%1,%2,%3};" \
        : "+f"((d)[0]), "+f"((d)[1]), "+f"((d)[2]), "+f"((d)[3]) \
        : "r"((a)[0]), "r"((a)[1]), "r"((a)[2]), "r"((a)[3]), "r"((b)[0]), "r"((b)[1]))

__device__ __forceinline__ float sfn_quant(float x) {
    float t = rintf(x * 2.0f);
    t = fminf(fmaxf(t, -8.0f), 8.0f);
    return t * 0.5f;
}
// boundary-risk flag: 1.5e-4 margin (~30 sigma vs bf16x3 GEMM error ~5e-6 RMS)
__device__ __forceinline__ bool sfn_risky(float v) {
    float t = v * 2.0f;
    float d = 0.5f - fabsf(t - rintf(t));
    return (d < 3e-4f) && (fabsf(t) < 8.51f);
}
__device__ __forceinline__ uint32_t packbf(float lo, float hi) {
    __nv_bfloat162 t = __floats2bfloat162_rn(lo, hi);
    return *reinterpret_cast<uint32_t*>(&t);
}

// ---------------------------------------------------------------------------
// fp32 -> (bf16 hi, bf16 lo) split
// ---------------------------------------------------------------------------
__device__ __forceinline__ void split_body(const float* __restrict__ X,
                                           __nv_bfloat16* __restrict__ hi,
                                           __nv_bfloat16* __restrict__ lo, int i) {
    float4 v = ((const float4*)X)[i];
    __nv_bfloat16 h0 = __float2bfloat16(v.x);
    __nv_bfloat16 h1 = __float2bfloat16(v.y);
    __nv_bfloat16 h2 = __float2bfloat16(v.z);
    __nv_bfloat16 h3 = __float2bfloat16(v.w);
    __nv_bfloat16 l0 = __float2bfloat16(v.x - __bfloat162float(h0));
    __nv_bfloat16 l1 = __float2bfloat16(v.y - __bfloat162float(h1));
    __nv_bfloat16 l2 = __float2bfloat16(v.z - __bfloat162float(h2));
    __nv_bfloat16 l3 = __float2bfloat16(v.w - __bfloat162float(h3));
    ((__nv_bfloat162*)hi)[2 * i + 0] = __halves2bfloat162(h0, h1);
    ((__nv_bfloat162*)hi)[2 * i + 1] = __halves2bfloat162(h2, h3);
    ((__nv_bfloat162*)lo)[2 * i + 0] = __halves2bfloat162(l0, l1);
    ((__nv_bfloat162*)lo)[2 * i + 1] = __halves2bfloat162(l2, l3);
}

__global__ void split_kernel(const float* __restrict__ X,
                             __nv_bfloat16* __restrict__ hi,
                             __nv_bfloat16* __restrict__ lo, int n4) {
    int i = blockIdx.x * blockDim.x + threadIdx.x;
    if (i < n4) split_body(X, hi, lo, i);
}

__global__ void split4_kernel(const float* __restrict__ W0, __nv_bfloat16* __restrict__ h0, __nv_bfloat16* __restrict__ l0,
                              const float* __restrict__ W1, __nv_bfloat16* __restrict__ h1, __nv_bfloat16* __restrict__ l1,
                              const float* __restrict__ W2, __nv_bfloat16* __restrict__ h2, __nv_bfloat16* __restrict__ l2,
                              const float* __restrict__ W3, __nv_bfloat16* __restrict__ h3, __nv_bfloat16* __restrict__ l3,
                              int n4) {
    int i = blockIdx.x * blockDim.x + threadIdx.x;
    if (i >= n4) return;
    const int z = blockIdx.y;
    if (z == 0)      split_body(W0, h0, l0, i);
    else if (z == 1) split_body(W1, h1, l1, i);
    else if (z == 2) split_body(W2, h2, l2, i);
    else             split_body(W3, h3, l3, i);
}

// ---------------------------------------------------------------------------
// mma.sync bf16x3 GEMM-NT. BM=128, BN=256, BK=32. 8 warps as 2m x 4n,
// warp tile 64x64. 3-stage cp.async pipeline.
// ---------------------------------------------------------------------------
#define BM 128
#define BN 256
#define BK 32
#define NCHUNK (DMODEL / BK)     // 32
#define ROWB 80
#define OFF_AHI 0
#define OFF_ALO 10240
#define OFF_WHI 20480
#define OFF_WLO 40960
#define STAGE_BYTES 61440
#define NSTAGE 3
#define GEMM_SMEM (NSTAGE * STAGE_BYTES)   // 184320

__device__ __forceinline__ void gemm_issue_loads(
    uint32_t sb, int buf, int chunk,
    const __nv_bfloat16* __restrict__ Ahi, const __nv_bfloat16* __restrict__ Alo,
    const __nv_bfloat16* __restrict__ Whi, const __nv_bfloat16* __restrict__ Wlo,
    int m0, int n0, int tid) {
    const uint32_t b = sb + buf * STAGE_BYTES;
    const int k0 = chunk * BK;
#pragma unroll
    for (int j = 0; j < 2; ++j) {
        int slot = tid + j * 256;
        int r = slot >> 2, c = slot & 3;
        uint32_t so = (uint32_t)(r * ROWB + c * 16);
        size_t ga = (size_t)(m0 + r) * DMODEL + k0 + c * 8;
        CP16(b + OFF_AHI + so, Ahi + ga);
        CP16(b + OFF_ALO + so, Alo + ga);
    }
#pragma unroll
    for (int j = 0; j < 4; ++j) {
        int slot = tid + j * 256;
        int r = slot >> 2, c = slot & 3;
        uint32_t so = (uint32_t)(r * ROWB + c * 16);
        size_t gw = (size_t)(n0 + r) * DMODEL + k0 + c * 8;
        CP16(b + OFF_WHI + so, Whi + gw);
        CP16(b + OFF_WLO + so, Wlo + gw);
    }
}

template <bool DO_SFN>
__global__ void __launch_bounds__(256, 1)
gemm_mma_kernel(const __nv_bfloat16* __restrict__ Ahi, const __nv_bfloat16* __restrict__ Alo,
                const __nv_bfloat16* __restrict__ W0h, const __nv_bfloat16* __restrict__ W0l,
                const float* __restrict__ b0, void* __restrict__ C0v,
                const __nv_bfloat16* __restrict__ W1h, const __nv_bfloat16* __restrict__ W1l,
                const float* __restrict__ b1, void* __restrict__ C1v,
                const __nv_bfloat16* __restrict__ W2h, const __nv_bfloat16* __restrict__ W2l,
                const float* __restrict__ b2, void* __restrict__ C2v,
                int* __restrict__ fixcnt, uint32_t* __restrict__ fixlist) {
    const __nv_bfloat16 *Whi, *Wlo;
    const float* bias;
    void* Cv;
    const int z = blockIdx.z;
    if (z == 0)      { Whi = W0h; Wlo = W0l; bias = b0; Cv = C0v; }
    else if (z == 1) { Whi = W1h; Wlo = W1l; bias = b1; Cv = C1v; }
    else             { Whi = W2h; Wlo = W2l; bias = b2; Cv = C2v; }

    extern __shared__ char smem[];
    const uint32_t sb = smem_u32(smem);
    const int tid = threadIdx.x;
    const int wid = tid >> 5;
    const int lane = tid & 31;
    const int warp_m = wid & 1;
    const int warp_n = wid >> 1;
    const int m0 = blockIdx.y * BM;
    const int n0 = blockIdx.x * BN;

    float acc[4][8][4];
#pragma unroll
    for (int mt = 0; mt < 4; ++mt)
#pragma unroll
        for (int nt = 0; nt < 8; ++nt)
#pragma unroll
            for (int e = 0; e < 4; ++e) acc[mt][nt][e] = 0.0f;

    const uint32_t a_off = (uint32_t)((warp_m * 64 + (lane & 15)) * ROWB
                                      + ((lane >> 4) & 1) * 16);
    const uint32_t b_off = (uint32_t)((warp_n * 64 + ((lane >> 4) & 1) * 8 + (lane & 7)) * ROWB
                                      + ((lane >> 3) & 1) * 16);

    gemm_issue_loads(sb, 0, 0, Ahi, Alo, Whi, Wlo, m0, n0, tid); CP_COMMIT();
    gemm_issue_loads(sb, 1, 1, Ahi, Alo, Whi, Wlo, m0, n0, tid); CP_COMMIT();
    gemm_issue_loads(sb, 2, 2, Ahi, Alo, Whi, Wlo, m0, n0, tid); CP_COMMIT();

    int buf = 0;
    for (int i = 0; i < NCHUNK; ++i) {
        if (i + 2 < NCHUNK) { CP_WAIT(2); } else if (i + 1 < NCHUNK) { CP_WAIT(1); } else { CP_WAIT(0); }
        __syncthreads();

        const uint32_t st = sb + buf * STAGE_BYTES;
#pragma unroll
        for (int ks = 0; ks < 2; ++ks) {
            uint32_t ah[4][4], al[4][4];
#pragma unroll
            for (int mt = 0; mt < 4; ++mt) {
                uint32_t ao = a_off + (uint32_t)(mt * 16 * ROWB + ks * 32);
                LDSM4(ah[mt][0], ah[mt][1], ah[mt][2], ah[mt][3], st + OFF_AHI + ao);
                LDSM4(al[mt][0], al[mt][1], al[mt][2], al[mt][3], st + OFF_ALO + ao);
            }
#pragma unroll
            for (int ntp = 0; ntp < 4; ++ntp) {
                uint32_t bo = b_off + (uint32_t)(ntp * 16 * ROWB + ks * 32);
                uint32_t wh[4], wl[4];
                LDSM4(wh[0], wh[1], wh[2], wh[3], st + OFF_WHI + bo);
                LDSM4(wl[0], wl[1], wl[2], wl[3], st + OFF_WLO + bo);
                uint32_t bh0[2] = {wh[0], wh[1]};
                uint32_t bh1[2] = {wh[2], wh[3]};
                uint32_t bl0[2] = {wl[0], wl[1]};
                uint32_t bl1[2] = {wl[2], wl[3]};
#pragma unroll
                for (int mt = 0; mt < 4; ++mt) {
                    MMA_BF16(acc[mt][2 * ntp],     ah[mt], bh0);
                    MMA_BF16(acc[mt][2 * ntp],     ah[mt], bl0);
                    MMA_BF16(acc[mt][2 * ntp],     al[mt], bh0);
                    MMA_BF16(acc[mt][2 * ntp + 1], ah[mt], bh1);
                    MMA_BF16(acc[mt][2 * ntp + 1], ah[mt], bl1);
                    MMA_BF16(acc[mt][2 * ntp + 1], al[mt], bh1);
                }
            }
        }
        __syncthreads();

        if (i + 3 < NCHUNK) {
            gemm_issue_loads(sb, buf, i + 3, Ahi, Alo, Whi, Wlo, m0, n0, tid);
            CP_COMMIT();
        }
        if (++buf == NSTAGE) buf = 0;
    }

    const int col_base = n0 + warp_n * 64 + (lane & 3) * 2;
    int* cnt = fixcnt + z;
    uint32_t* list = fixlist + (size_t)z * FIX_CAP;
#pragma unroll
    for (int mt = 0; mt < 4; ++mt) {
        const int row_base = m0 + warp_m * 64 + mt * 16 + (lane >> 2);
#pragma unroll
        for (int nt = 0; nt < 8; ++nt) {
            const int col = col_base + nt * 8;
            const float bb0 = __ldg(bias + col);
            const float bb1 = __ldg(bias + col + 1);
            const int r0 = row_base;
            float v0 = acc[mt][nt][0] + bb0;
            float v1 = acc[mt][nt][1] + bb1;
            float v2 = acc[mt][nt][2] + bb0;
            float v3 = acc[mt][nt][3] + bb1;
            if (DO_SFN) {
                if (sfn_risky(v0)) { int ix = atomicAdd(cnt, 1); if (ix < FIX_CAP) list[ix] = ((uint32_t)r0 << 10) | col; }
                if (sfn_risky(v1)) { int ix = atomicAdd(cnt, 1); if (ix < FIX_CAP) list[ix] = ((uint32_t)r0 << 10) | (col + 1); }
                if (sfn_risky(v2)) { int ix = atomicAdd(cnt, 1); if (ix < FIX_CAP) list[ix] = ((uint32_t)(r0 + 8) << 10) | col; }
                if (sfn_risky(v3)) { int ix = atomicAdd(cnt, 1); if (ix < FIX_CAP) list[ix] = ((uint32_t)(r0 + 8) << 10) | (col + 1); }
                __nv_bfloat16* Cb = (__nv_bfloat16*)Cv;
                *(uint32_t*)(Cb + (size_t)r0 * DMODEL + col) = packbf(sfn_quant(v0), sfn_quant(v1));
                *(uint32_t*)(Cb + (size_t)(r0 + 8) * DMODEL + col) = packbf(sfn_quant(v2), sfn_quant(v3));
            } else {
                float* C = (float*)Cv;
                *(float2*)(C + (size_t)r0 * DMODEL + col) = make_float2(v0, v1);
                *(float2*)(C + (size_t)(r0 + 8) * DMODEL + col) = make_float2(v2, v3);
            }
        }
    }
}

// ---------------------------------------------------------------------------
// Fixup: recompute flagged elements exactly in fp32. One warp per element,
// heavily parallel (grid 256 x 3).
// ---------------------------------------------------------------------------
__global__ void fixup_kernel(const float* __restrict__ X,
                             const float* __restrict__ W0, const float* __restrict__ bia0, __nv_bfloat16* __restrict__ C0,
                             const float* __restrict__ W1, const float* __restrict__ bia1, __nv_bfloat16* __restrict__ C1,
                             const float* __restrict__ W2, const float* __restrict__ bia2, __nv_bfloat16* __restrict__ C2,
                             const int* __restrict__ fixcnt, const uint32_t* __restrict__ fixlist) {
    const int z = blockIdx.y;
    const float* W;
    const float* bias;
    __nv_bfloat16* C;
    if (z == 0)      { W = W0; bias = bia0; C = C0; }
    else if (z == 1) { W = W1; bias = bia1; C = C1; }
    else             { W = W2; bias = bia2; C = C2; }

    int n = fixcnt[z];
    if (n > FIX_CAP) n = FIX_CAP;
    const uint32_t* list = fixlist + (size_t)z * FIX_CAP;

    const int lane = threadIdx.x & 31;
    const int warp = (blockIdx.x * blockDim.x + threadIdx.x) >> 5;
    const int nwarps = (gridDim.x * blockDim.x) >> 5;

    for (int e = warp; e < n; e += nwarps) {
        uint32_t u = list[e];
        int row = u >> 10;
        int col = u & 1023;
        const float* xr = X + (size_t)row * DMODEL;
        const float* wr = W + (size_t)col * DMODEL;
        float s = 0.0f;
#pragma unroll
        for (int j = 0; j < DMODEL / 32; ++j)
            s = fmaf(xr[lane + j * 32], wr[lane + j * 32], s);
#pragma unroll
        for (int o = 16; o; o >>= 1) s += __shfl_xor_sync(0xffffffffu, s, o);
        if (lane == 0)
            C[(size_t)row * DMODEL + col] = __float2bfloat16(sfn_quant(s + bias[col]));
    }
}

// ---------------------------------------------------------------------------
// Prep: irq/irk, q~ hi/lo, and qlo-nonzero flag.
// ---------------------------------------------------------------------------
__global__ void prep_kernel(const __nv_bfloat16* __restrict__ qb,
                            const __nv_bfloat16* __restrict__ kb,
                            const float* __restrict__ gq, const float* __restrict__ gk,
                            __nv_bfloat16* __restrict__ qthi, __nv_bfloat16* __restrict__ qtlo,
                            float* __restrict__ irq, float* __restrict__ irk,
                            int* __restrict__ qlo_flag) {
    const int gwarp = (blockIdx.x * blockDim.x + threadIdx.x) >> 5;
    const int lane = threadIdx.x & 31;
    const int token = gwarp >> 4;
    const int h = gwarp & 15;
    const size_t base = (size_t)token * DMODEL + h * HDIM + lane * 2;

    __nv_bfloat162 q2 = *(const __nv_bfloat162*)(qb + base);
    __nv_bfloat162 k2 = *(const __nv_bfloat162*)(kb + base);
    float qx = __bfloat162float(q2.x), qy = __bfloat162float(q2.y);
    float kx = __bfloat162float(k2.x), ky = __bfloat162float(k2.y);
    float sq = qx * qx + qy * qy;
    float sk = kx * kx + ky * ky;
#pragma unroll
    for (int o = 16; o; o >>= 1) {
        sq += __shfl_xor_sync(0xffffffffu, sq, o);
        sk += __shfl_xor_sync(0xffffffffu, sk, o);
    }
    if (lane == 0) {
        irq[(size_t)h * TOKENS + token] = rsqrtf(sq * (1.0f / 64.0f) + 1e-6f);
        irk[(size_t)h * TOKENS + token] = rsqrtf(sk * (1.0f / 64.0f) + 1e-6f);
    }
    float gg0 = gq[lane * 2] * gk[lane * 2];
    float gg1 = gq[lane * 2 + 1] * gk[lane * 2 + 1];
    float t0 = qx * gg0, t1 = qy * gg1;
    float h0 = __bfloat162float(__float2bfloat16(t0));
    float h1 = __bfloat162float(__float2bfloat16(t1));
    uint32_t lopack = packbf(t0 - h0, t1 - h1);
    *(uint32_t*)(qthi + base) = packbf(h0, h1);
    *(uint32_t*)(qtlo + base) = lopack;
    if (__any_sync(0xffffffffu, lopack != 0u)) {
        if (lane == 0) atomicOr(qlo_flag, 1);
    }
}

// ---------------------------------------------------------------------------
// Flash attention, mma.sync bf16. log2-domain softmax; optional ql stream.
// ---------------------------------------------------------------------------
#define AROWB 144
#define SM_QHI 0
#define SM_QLO 9216
#define SM_K   18432
#define SM_V   36864
#define SM_IRK 55296
#define ATTN_SMEM 55808

__global__ void __launch_bounds__(128, 1)
attn_mma_kernel(const __nv_bfloat16* __restrict__ qthi,
                const __nv_bfloat16* __restrict__ qtlo,
                const __nv_bfloat16* __restrict__ kb,
                const __nv_bfloat16* __restrict__ vb,
                const float* __restrict__ irqg, const float* __restrict__ irkg,
                const int* __restrict__ qlo_flag,
                __nv_bfloat16* __restrict__ ahi, __nv_bfloat16* __restrict__ alo) {
    extern __shared__ char smem[];
    const uint32_t sb = smem_u32(smem);
    const int tid = threadIdx.x;
    const int wid = tid >> 5;
    const int lane = tid & 31;
    const int gid = lane >> 2;
    const int tig = lane & 3;
    const int qb_ = blockIdx.x;
    const int h = blockIdx.y;
    const int b = blockIdx.z;
    const int tq = b * SEQ + qb_ * 64;
    const int qlnz = *qlo_flag;

#pragma unroll
    for (int it = 0; it < 4; ++it) {
        int c = tid + it * 128;
        int r = c >> 3, cc = c & 7;
        size_t g = (size_t)(tq + r) * DMODEL + h * HDIM + cc * 8;
        CP16(sb + SM_QHI + r * AROWB + cc * 16, qthi + g);
        if (qlnz) CP16(sb + SM_QLO + r * AROWB + cc * 16, qtlo + g);
    }
    CP_COMMIT();
#pragma unroll
    for (int pb = 0; pb < 2; ++pb) {
        int tk = b * SEQ + pb * 64;
#pragma unroll
        for (int it = 0; it < 4; ++it) {
            int c = tid + it * 128;
            int r = c >> 3, cc = c & 7;
            size_t g = (size_t)(tk + r) * DMODEL + h * HDIM + cc * 8;
            CP16(sb + SM_K + pb * 9216 + r * AROWB + cc * 16, kb + g);
            CP16(sb + SM_V + pb * 9216 + r * AROWB + cc * 16, vb + g);
        }
        if (tid < 16)
            CP16(sb + SM_IRK + pb * 256 + tid * 16, irkg + (size_t)h * TOKENS + tk + tid * 4);
        CP_COMMIT();
    }
    CP_WAIT(2);
    __syncthreads();

    uint32_t qh[4][4], ql[4][4];
    {
        uint32_t bqh = sb + SM_QHI + (wid * 16 + (lane & 15)) * AROWB + ((lane >> 4) & 1) * 16;
        uint32_t bql = sb + SM_QLO + (wid * 16 + (lane & 15)) * AROWB + ((lane >> 4) & 1) * 16;
#pragma unroll
        for (int kc = 0; kc < 4; ++kc) {
            LDSM4(qh[kc][0], qh[kc][1], qh[kc][2], qh[kc][3], bqh + kc * 32);
            if (qlnz) LDSM4(ql[kc][0], ql[kc][1], ql[kc][2], ql[kc][3], bql + kc * 32);
        }
    }
    const float irq0 = irqg[(size_t)h * TOKENS + tq + wid * 16 + gid];
    const float irq1 = irqg[(size_t)h * TOKENS + tq + wid * 16 + gid + 8];
    const float sc0 = 0.125f * LOG2E * irq0;
    const float sc1 = 0.125f * LOG2E * irq1;

    const uint32_t kf_off = (uint32_t)((((lane >> 4) & 1) * 8 + (lane & 7)) * AROWB
                                       + ((lane >> 3) & 1) * 16);

    float m0 = -1e30f, m1 = -1e30f, l0 = 0.0f, l1 = 0.0f;
    float o[8][4];
#pragma unroll
    for (int d = 0; d < 8; ++d)
#pragma unroll
        for (int e = 0; e < 4; ++e) o[d][e] = 0.0f;

    for (int kbi = 0; kbi < SEQ / 64; ++kbi) {
        if (kbi < SEQ / 64 - 1) { CP_WAIT(1); } else { CP_WAIT(0); }
        __syncthreads();
        const int buf = kbi & 1;
        const uint32_t Kb = sb + SM_K + buf * 9216;
        const uint32_t Vb = sb + SM_V + buf * 9216;

        float2 irk2[8];
#pragma unroll
        for (int j = 0; j < 8; ++j)
            irk2[j] = *(const float2*)(smem + SM_IRK + buf * 256 + (8 * j + 2 * tig) * 4);

        float s[8][4];
#pragma unroll
        for (int j = 0; j < 8; ++j)
#pragma unroll
            for (int e = 0; e < 4; ++e) s[j][e] = 0.0f;

        if (qlnz) {
#pragma unroll
            for (int kc = 0; kc < 4; ++kc) {
#pragma unroll
                for (int jp = 0; jp < 4; ++jp) {
                    uint32_t kf[4];
                    LDSM4(kf[0], kf[1], kf[2], kf[3], Kb + kf_off + jp * 16 * AROWB + kc * 32);
                    uint32_t f0[2] = {kf[0], kf[1]};
                    uint32_t f1[2] = {kf[2], kf[3]};
                    MMA_BF16(s[2 * jp], qh[kc], f0);
                    MMA_BF16(s[2 * jp], ql[kc], f0);
                    MMA_BF16(s[2 * jp + 1], qh[kc], f1);
                    MMA_BF16(s[2 * jp + 1], ql[kc], f1);
                }
            }
        } else {
#pragma unroll
            for (int kc = 0; kc < 4; ++kc) {
#pragma unroll
                for (int jp = 0; jp < 4; ++jp) {
                    uint32_t kf[4];
                    LDSM4(kf[0], kf[1], kf[2], kf[3], Kb + kf_off + jp * 16 * AROWB + kc * 32);
                    uint32_t f0[2] = {kf[0], kf[1]};
                    uint32_t f1[2] = {kf[2], kf[3]};
                    MMA_BF16(s[2 * jp], qh[kc], f0);
                    MMA_BF16(s[2 * jp + 1], qh[kc], f1);
                }
            }
        }

        float rm0 = -1e30f, rm1 = -1e30f;
#pragma unroll
        for (int j = 0; j < 8; ++j) {
            s[j][0] *= sc0 * irk2[j].x;
            s[j][1] *= sc0 * irk2[j].y;
            s[j][2] *= sc1 * irk2[j].x;
            s[j][3] *= sc1 * irk2[j].y;
            rm0 = fmaxf(rm0, fmaxf(s[j][0], s[j][1]));
            rm1 = fmaxf(rm1, fmaxf(s[j][2], s[j][3]));
        }
        rm0 = fmaxf(rm0, __shfl_xor_sync(0xffffffffu, rm0, 1));
        rm0 = fmaxf(rm0, __shfl_xor_sync(0xffffffffu, rm0, 2));
        rm1 = fmaxf(rm1, __shfl_xor_sync(0xffffffffu, rm1, 1));
        rm1 = fmaxf(rm1, __shfl_xor_sync(0xffffffffu, rm1, 2));
        const float mn0 = fmaxf(m0, rm0);
        const float mn1 = fmaxf(m1, rm1);
        const float al0 = exp2f(m0 - mn0);
        const float al1 = exp2f(m1 - mn1);
        m0 = mn0; m1 = mn1;
        float rs0 = 0.0f, rs1 = 0.0f;
#pragma unroll
        for (int j = 0; j < 8; ++j) {
            s[j][0] = exp2f(s[j][0] - mn0);
            s[j][1] = exp2f(s[j][1] - mn0);
            s[j][2] = exp2f(s[j][2] - mn1);
            s[j][3] = exp2f(s[j][3] - mn1);
            rs0 += s[j][0] + s[j][1];
            rs1 += s[j][2] + s[j][3];
        }
        rs0 += __shfl_xor_sync(0xffffffffu, rs0, 1);
        rs0 += __shfl_xor_sync(0xffffffffu, rs0, 2);
        rs1 += __shfl_xor_sync(0xffffffffu, rs1, 1);
        rs1 += __shfl_xor_sync(0xffffffffu, rs1, 2);
        l0 = l0 * al0 + rs0;
        l1 = l1 * al1 + rs1;
#pragma unroll
        for (int d = 0; d < 8; ++d) {
            o[d][0] *= al0; o[d][1] *= al0;
            o[d][2] *= al1; o[d][3] *= al1;
        }

        uint32_t pah[4][4], pal[4][4];
#pragma unroll
        for (int jj = 0; jj < 4; ++jj) {
            float p00 = s[2 * jj][0], p01 = s[2 * jj][1], p02 = s[2 * jj][2], p03 = s[2 * jj][3];
            float p10 = s[2 * jj + 1][0], p11 = s[2 * jj + 1][1], p12 = s[2 * jj + 1][2], p13 = s[2 * jj + 1][3];
            float h00 = __bfloat162float(__float2bfloat16(p00));
            float h01 = __bfloat162float(__float2bfloat16(p01));
            float h02 = __bfloat162float(__float2bfloat16(p02));
            float h03 = __bfloat162float(__float2bfloat16(p03));
            float h10 = __bfloat162float(__float2bfloat16(p10));
            float h11 = __bfloat162float(__float2bfloat16(p11));
            float h12 = __bfloat162float(__float2bfloat16(p12));
            float h13 = __bfloat162float(__float2bfloat16(p13));
            pah[jj][0] = packbf(h00, h01);
            pah[jj][1] = packbf(h02, h03);
            pah[jj][2] = packbf(h10, h11);
            pah[jj][3] = packbf(h12, h13);
            pal[jj][0] = packbf(p00 - h00, p01 - h01);
            pal[jj][1] = packbf(p02 - h02, p03 - h03);
            pal[jj][2] = packbf(p10 - h10, p11 - h11);
            pal[jj][3] = packbf(p12 - h12, p13 - h13);
        }

#pragma unroll
        for (int jj = 0; jj < 4; ++jj) {
#pragma unroll
            for (int dp = 0; dp < 4; ++dp) {
                uint32_t v0, v1, v2, v3;
                LDSM4T(v0, v1, v2, v3,
                       Vb + (jj * 16 + (lane & 15)) * AROWB + dp * 32 + ((lane >> 4) & 1) * 16);
                uint32_t vb0[2] = {v0, v1};
                uint32_t vb1[2] = {v2, v3};
                MMA_BF16(o[2 * dp], pah[jj], vb0);
                MMA_BF16(o[2 * dp], pal[jj], vb0);
                MMA_BF16(o[2 * dp + 1], pah[jj], vb1);
                MMA_BF16(o[2 * dp + 1], pal[jj], vb1);
            }
        }
        __syncthreads();

        if (kbi + 2 < SEQ / 64) {
            int tk = b * SEQ + (kbi + 2) * 64;
#pragma unroll
            for (int it = 0; it < 4; ++it) {
                int c = tid + it * 128;
                int r = c >> 3, cc = c & 7;
                size_t g = (size_t)(tk + r) * DMODEL + h * HDIM + cc * 8;
                CP16(sb + SM_K + buf * 9216 + r * AROWB + cc * 16, kb + g);
                CP16(sb + SM_V + buf * 9216 + r * AROWB + cc * 16, vb + g);
            }
            if (tid < 16)
                CP16(sb + SM_IRK + buf * 256 + tid * 16, irkg + (size_t)h * TOKENS + tk + tid * 4);
            CP_COMMIT();
        }
    }

    const float invl0 = 1.0f / l0;
    const float invl1 = 1.0f / l1;
    const int row0 = tq + wid * 16 + gid;
#pragma unroll
    for (int d = 0; d < 8; ++d) {
        const int col = h * HDIM + d * 8 + tig * 2;
        float x0 = o[d][0] * invl0, x1 = o[d][1] * invl0;
        float x2 = o[d][2] * invl1, x3 = o[d][3] * invl1;
        float h0 = __bfloat162float(__float2bfloat16(x0));
        float h1 = __bfloat162float(__float2bfloat16(x1));
        float h2 = __bfloat162float(__float2bfloat16(x2));
        float h3 = __bfloat162float(__float2bfloat16(x3));
        *(uint32_t*)(ahi + (size_t)row0 * DMODEL + col) = packbf(h0, h1);
        *(uint32_t*)(alo + (size_t)row0 * DMODEL + col) = packbf(x0 - h0, x1 - h1);
        *(uint32_t*)(ahi + (size_t)(row0 + 8) * DMODEL + col) = packbf(h2, h3);
        *(uint32_t*)(alo + (size_t)(row0 + 8) * DMODEL + col) = packbf(x2 - h2, x3 - h3);
    }
}

// ---------------------------------------------------------------------------

extern "C" void kernel_launch(void* const* d_in, const int* in_sizes, int n_in,
                              void* d_out, int out_size) {
    const float* x  = (const float*)d_in[0];
    const float* Wq = (const float*)d_in[1];
    const float* bq = (const float*)d_in[2];
    const float* Wk = (const float*)d_in[3];
    const float* bk = (const float*)d_in[4];
    const float* Wv = (const float*)d_in[5];
    const float* bv = (const float*)d_in[6];
    const float* Wo = (const float*)d_in[7];
    const float* bo = (const float*)d_in[8];
    const float* gq = (const float*)d_in[9];
    const float* gk = (const float*)d_in[10];
    float* out = (float*)d_out;

    __nv_bfloat16 *qb, *kbp, *vbp, *qthi, *qtlo, *ahi, *alo, *xhi, *xlo;
    __nv_bfloat16 *wqh, *wql, *wkh, *wkl, *wvh, *wvl, *woh, *wol;
    float *irq, *irk;
    cudaGetSymbolAddress((void**)&qb, g_qb);
    cudaGetSymbolAddress((void**)&kbp, g_kb);
    cudaGetSymbolAddress((void**)&vbp, g_vb);
    cudaGetSymbolAddress((void**)&qthi, g_qthi);
    cudaGetSymbolAddress((void**)&qtlo, g_qtlo);
    cudaGetSymbolAddress((void**)&ahi, g_ahi);
    cudaGetSymbolAddress((void**)&alo, g_alo);
    cudaGetSymbolAddress((void**)&xhi, g_xhi);
    cudaGetSymbolAddress((void**)&xlo, g_xlo);
    cudaGetSymbolAddress((void**)&wqh, g_wqhi);
    cudaGetSymbolAddress((void**)&wql, g_wqlo);
    cudaGetSymbolAddress((void**)&wkh, g_wkhi);
    cudaGetSymbolAddress((void**)&wkl, g_wklo);
    cudaGetSymbolAddress((void**)&wvh, g_wvhi);
    cudaGetSymbolAddress((void**)&wvl, g_wvlo);
    cudaGetSymbolAddress((void**)&woh, g_wohi);
    cudaGetSymbolAddress((void**)&wol, g_wolo);
    cudaGetSymbolAddress((void**)&irq, g_irq);
    cudaGetSymbolAddress((void**)&irk, g_irk);
    int* fixcnt;
    uint32_t* fixlist;
    cudaGetSymbolAddress((void**)&fixcnt, g_fixcnt);
    cudaGetSymbolAddress((void**)&fixlist, g_fixlist);

    cudaFuncSetAttribute(gemm_mma_kernel<true>,
                         cudaFuncAttributeMaxDynamicSharedMemorySize, GEMM_SMEM);
    cudaFuncSetAttribute(gemm_mma_kernel<false>,
                         cudaFuncAttributeMaxDynamicSharedMemorySize, GEMM_SMEM);
    cudaFuncSetAttribute(attn_mma_kernel,
                         cudaFuncAttributeMaxDynamicSharedMemorySize, ATTN_SMEM);

    cudaMemsetAsync(fixcnt, 0, 4 * sizeof(int));

    const int NX4 = TOKENS * DMODEL / 4;
    const int NW4 = DMODEL * DMODEL / 4;
    split_kernel<<<NX4 / 256, 256>>>(x, xhi, xlo, NX4);
    split4_kernel<<<dim3(NW4 / 256, 4), 256>>>(Wq, wqh, wql, Wk, wkh, wkl,
                                               Wv, wvh, wvl, Wo, woh, wol, NW4);

    gemm_mma_kernel<true><<<dim3(DMODEL / BN, TOKENS / BM, 3), 256, GEMM_SMEM>>>(
        xhi, xlo,
        wqh, wql, bq, qb,
        wkh, wkl, bk, kbp,
        wvh, wvl, bv, vbp,
        fixcnt, fixlist);

    // Highly parallel fixup: 256 blocks per matrix
    fixup_kernel<<<dim3(256, 3), 256>>>(x, Wq, bq, qb, Wk, bk, kbp, Wv, bv, vbp,
                                        fixcnt, fixlist);

    prep_kernel<<<(TOKENS * NHEAD) / 8, 256>>>(qb, kbp, gq, gk, qthi, qtlo,
                                               irq, irk, fixcnt + 3);

    attn_mma_kernel<<<dim3(SEQ / 64, NHEAD, BATCH), 128, ATTN_SMEM>>>(
        qthi, qtlo, kbp, vbp, irq, irk, fixcnt + 3, ahi, alo);

    gemm_mma_kernel<false><<<dim3(DMODEL / BN, TOKENS / BM, 1), 256, GEMM_SMEM>>>(
        ahi, alo,
        woh, wol, bo, out,
        woh, wol, bo, out,
        woh, wol, bo, out,
        fixcnt + 3, fixlist);
}